// round 10
// baseline (speedup 1.0000x reference)
#include <cuda_runtime.h>
#include <cuda_bf16.h>
#include <cstdint>

#define N_NODES 50000
#define N_EDGES 1000000
#define HIDDEN  128
#define N_GAUSS 50
#define N_FILT  128
#define N_COLORS 4
#define CUTOFF_R 10.0f
#define LOG2F_  0.6931471805599453f
#define PI_F    3.14159265358979323846f

#define CH 1024              // edges per block-chunk (color-aligned)
#define NCHUNK 981
#define PERM_SZ (NCHUNK*CH)
#define SC_BS 4096
#define SC_NB 245
#define L1_NB 391
#define FULLM 0xffffffffu

// ---- scratch (static device globals; zero-initialized at module load) ----
__device__ float g_h[N_NODES * HIDDEN];
__device__ float g_agg[N_NODES * N_FILT];
__device__ int   g_perm[PERM_SZ];           // color-sorted (edge id + 1), 0 = pad
__device__ int   g_cnt[N_COLORS];
__device__ int   g_cur[N_COLORS];

__device__ __forceinline__ float ssp(float v) {
    return fmaxf(v, 0.0f) + __logf(1.0f + __expf(-fabsf(v))) - LOG2F_;
}

typedef uint32_t u32;

// pack two f32 -> bf16x2 {lo, hi}
__device__ __forceinline__ u32 pk_bf(float lo, float hi) {
    u32 r;
    asm("cvt.rn.bf16x2.f32 %0, %1, %2;" : "=r"(r) : "f"(hi), "f"(lo));
    return r;
}
__device__ __forceinline__ float bfr(float v) {   // residual after bf16 truncation
    return v - __bfloat162float(__float2bfloat16(v));
}

// m16n8k16 row.col f32.bf16.bf16.f32
#define MMA16816(d, a, b) \
    asm volatile("mma.sync.aligned.m16n8k16.row.col.f32.bf16.bf16.f32 " \
        "{%0,%1,%2,%3}, {%4,%5,%6,%7}, {%8,%9}, {%0,%1,%2,%3};" \
        : "+f"((d)[0]), "+f"((d)[1]), "+f"((d)[2]), "+f"((d)[3]) \
        : "r"((a)[0]), "r"((a)[1]), "r"((a)[2]), "r"((a)[3]), \
          "r"((b)[0]), "r"((b)[1]))

// ---------------------------------------------------------------- histogram
__global__ void hist_kernel(const int* __restrict__ colors) {
    __shared__ int sh[N_COLORS];
    if (threadIdx.x < N_COLORS) sh[threadIdx.x] = 0;
    __syncthreads();
    int idx = blockIdx.x * blockDim.x + threadIdx.x;
    int stride = gridDim.x * blockDim.x;
    for (int i = idx; i < N_EDGES; i += stride) atomicAdd(&sh[colors[i]], 1);
    __syncthreads();
    if (threadIdx.x < N_COLORS) atomicAdd(&g_cnt[threadIdx.x], sh[threadIdx.x]);
}

// ---------------------------------------------------------------- offsets
__global__ void offset_kernel() {
    if (blockIdx.x == 0 && threadIdx.x == 0) {
        int b = 0;
        for (int c = 0; c < N_COLORS; c++) {
            g_cur[c] = b;
            b += (g_cnt[c] + CH - 1) / CH * CH;
        }
    }
}

// ---------------------------------------------------------------- scatter + lin1 (fused)
__global__ void __launch_bounds__(256) scatter_lin1_kernel(
    const int* __restrict__ colors,
    const float* __restrict__ x,
    const float* __restrict__ w)
{
    extern __shared__ float smf[];
    if (blockIdx.x < SC_NB) {
        __shared__ int s_cnt[N_COLORS], s_base[N_COLORS];
        int t = threadIdx.x;
        if (t < N_COLORS) s_cnt[t] = 0;
        __syncthreads();
        int start = blockIdx.x * SC_BS;
        int end = min(start + SC_BS, N_EDGES);
        for (int i = start + t; i < end; i += blockDim.x) atomicAdd(&s_cnt[colors[i]], 1);
        __syncthreads();
        if (t < N_COLORS) { s_base[t] = atomicAdd(&g_cur[t], s_cnt[t]); s_cnt[t] = 0; }
        __syncthreads();
        for (int i = start + t; i < end; i += blockDim.x) {
            int c = colors[i];
            int pos = s_base[c] + atomicAdd(&s_cnt[c], 1);
            g_perm[pos] = i + 1;
        }
    } else {
        int tile = blockIdx.x - SC_NB;
        float* Wt = smf;
        float* xs = Wt + 16384;
        int t = threadIdx.x;
        int th = t & 127, half = t >> 7;
        for (int i = t; i < 16384; i += 256) {
            int f = i >> 7, k = i & 127;
            Wt[k * 128 + f] = w[i];
        }
        __syncthreads();
        int row0 = tile * 128;
        for (int rg = 0; rg < 128; rg += 8) {
            int r = row0 + rg + half * 4;
#pragma unroll
            for (int j = 0; j < 4; j++) {
                int rr = r + j;
                xs[(half * 4 + j) * 128 + th] = (rr < N_NODES) ? x[rr * 128 + th] : 0.0f;
            }
            __syncthreads();
            float a0 = 0, a1 = 0, a2 = 0, a3 = 0;
#pragma unroll 8
            for (int k = 0; k < 128; k++) {
                float wv = Wt[k * 128 + th];
                a0 += xs[(half * 4 + 0) * 128 + k] * wv;
                a1 += xs[(half * 4 + 1) * 128 + k] * wv;
                a2 += xs[(half * 4 + 2) * 128 + k] * wv;
                a3 += xs[(half * 4 + 3) * 128 + k] * wv;
            }
            if (r + 0 < N_NODES) g_h[(r + 0) * 128 + th] = a0;
            if (r + 1 < N_NODES) g_h[(r + 1) * 128 + th] = a1;
            if (r + 2 < N_NODES) g_h[(r + 2) * 128 + th] = a2;
            if (r + 3 < N_NODES) g_h[(r + 3) * 128 + th] = a3;
            __syncthreads();
        }
    }
}

// ---------------------------------------------------------------- HMMA fused edge kernel
// 256 threads = 8 warps; each warp owns 128 edges of the 1024-edge chunk,
// processed 16 at a time (one m16 tile). bf16 hi/lo 3-term compensated mma.
// MLP1's D fragments convert IN REGISTERS into MLP2's A fragments (layouts match).
//
// SMEM (u32 words):
#define O_W1H  0            // [128 f][36]  (32 k-pair words used, stride 36 for banks)
#define O_W1L  4608
#define O_W2H  9216         // [128 f][68]  (64 words used, stride 68)
#define O_W2L  17920
#define O_B1   26624        // 128 f32
#define O_B2   26752        // 128 f32
#define O_ATTR 26880        // 8 warps * [16 e][72] f32
#define O_META 36096        // 8 warps * 64: p[16] src[16] dst[16] C[16]
#define EDGE_SMEM ((36096 + 512) * 4)

__global__ void __launch_bounds__(256) edge_kernel(
    const int* __restrict__ edge_index,
    const float* __restrict__ ew,
    const float* __restrict__ attr,
    const int* __restrict__ colors,
    const float* __restrict__ m1w, const float* __restrict__ m1b,
    const float* __restrict__ m2w, const float* __restrict__ m2b)
{
    extern __shared__ u32 smu[];
    int t = threadIdx.x;
    int chunk0 = blockIdx.x * CH;
    int p0c = g_perm[chunk0] - 1;
    if (p0c < 0) return;                      // gap chunk (block-uniform)
    int c = colors[p0c];

    // ---- weight prep: bf16 hi/lo split into SMEM ----
    {
        const float* w1 = m1w + (size_t)c * 128 * N_GAUSS;
        for (int i = t; i < 128 * 32; i += 256) {
            int f = i >> 5, w = i & 31;
            int k0 = w * 2, k1 = w * 2 + 1;
            float v0 = (k0 < N_GAUSS) ? w1[f * N_GAUSS + k0] : 0.0f;
            float v1 = (k1 < N_GAUSS) ? w1[f * N_GAUSS + k1] : 0.0f;
            smu[O_W1H + f * 36 + w] = pk_bf(v0, v1);
            smu[O_W1L + f * 36 + w] = pk_bf(bfr(v0), bfr(v1));
        }
        const float* w2 = m2w + (size_t)c * 128 * 128;
        for (int i = t; i < 128 * 64; i += 256) {
            int f = i >> 6, w = i & 63;
            float2 v = *(const float2*)(w2 + f * 128 + w * 2);
            smu[O_W2H + f * 68 + w] = pk_bf(v.x, v.y);
            smu[O_W2L + f * 68 + w] = pk_bf(bfr(v.x), bfr(v.y));
        }
        if (t < 128) {
            ((float*)smu)[O_B1 + t] = m1b[c * 128 + t];
            ((float*)smu)[O_B2 + t] = m2b[c * 128 + t];
        }
    }
    __syncthreads();

    int wid = t >> 5, lane = t & 31;
    int gr = lane >> 2, tid = lane & 3;       // mma group-row / thread-in-group
    float* attr_w = (float*)(smu + O_ATTR) + wid * (16 * 72);
    int*   s_p    = (int*)(smu + O_META + wid * 64);
    int*   s_src  = s_p + 16;
    int*   s_dst  = s_p + 32;
    float* s_C    = (float*)(s_p + 48);
    const float* b1s = (const float*)(smu + O_B1);
    const float* b2s = (const float*)(smu + O_B2);

    for (int it = 0; it < 8; it++) {
        int ebase = chunk0 + wid * 128 + it * 16;

        // ---- metadata (lanes 0..15) ----
        if (lane < 16) {
            int p = g_perm[ebase + lane] - 1;
            int sr = 0, ds = -1;
            float C = 0.0f;
            if (p >= 0) {
                sr = edge_index[p];
                ds = edge_index[N_EDGES + p];
                C = 0.5f * (__cosf(ew[p] * (PI_F / CUTOFF_R)) + 1.0f);
            }
            s_p[lane] = p; s_src[lane] = sr; s_dst[lane] = ds; s_C[lane] = C;
        }
        __syncwarp();

        // ---- stage attr [16 e][64 g] f32 (zero-padded), stride 72 ----
        for (int i = lane; i < 16 * 64; i += 32) {
            int e = i >> 6, g = i & 63;
            int p = s_p[e];
            float v = (p >= 0 && g < N_GAUSS) ? __ldg(attr + (size_t)p * N_GAUSS + g) : 0.0f;
            attr_w[e * 72 + g] = v;
        }
        __syncwarp();

        // ---- attr A-fragments (hi/lo), K=64 -> 4 k-steps ----
        u32 AH1[4][4], AL1[4][4];
#pragma unroll
        for (int ks = 0; ks < 4; ks++) {
            float2 v0 = *(const float2*)(attr_w + gr * 72 + ks * 16 + tid * 2);
            float2 v1 = *(const float2*)(attr_w + (gr + 8) * 72 + ks * 16 + tid * 2);
            float2 v2 = *(const float2*)(attr_w + gr * 72 + ks * 16 + 8 + tid * 2);
            float2 v3 = *(const float2*)(attr_w + (gr + 8) * 72 + ks * 16 + 8 + tid * 2);
            AH1[ks][0] = pk_bf(v0.x, v0.y); AL1[ks][0] = pk_bf(bfr(v0.x), bfr(v0.y));
            AH1[ks][1] = pk_bf(v1.x, v1.y); AL1[ks][1] = pk_bf(bfr(v1.x), bfr(v1.y));
            AH1[ks][2] = pk_bf(v2.x, v2.y); AL1[ks][2] = pk_bf(bfr(v2.x), bfr(v2.y));
            AH1[ks][3] = pk_bf(v3.x, v3.y); AL1[ks][3] = pk_bf(bfr(v3.x), bfr(v3.y));
        }

        // ---- MLP1: D1 = attr @ W1^T, 16 n-tiles as 8 pairs; convert directly
        //      into MLP2 A-fragments (hidden never touches SMEM) ----
        u32 AH2[8][4], AL2[8][4];
#pragma unroll
        for (int np = 0; np < 8; np++) {
            float d0[4] = {0, 0, 0, 0}, d1[4] = {0, 0, 0, 0};
            int f0 = (2 * np) * 8 + gr;       // B-frag row for n-tile 2np
            int f1 = f0 + 8;                  // n-tile 2np+1
#pragma unroll
            for (int ks = 0; ks < 4; ks++) {
                u32 bh0[2], bl0[2], bh1[2], bl1[2];
                int w0 = ks * 8 + tid;
                bh0[0] = smu[O_W1H + f0 * 36 + w0]; bh0[1] = smu[O_W1H + f0 * 36 + w0 + 4];
                bl0[0] = smu[O_W1L + f0 * 36 + w0]; bl0[1] = smu[O_W1L + f0 * 36 + w0 + 4];
                bh1[0] = smu[O_W1H + f1 * 36 + w0]; bh1[1] = smu[O_W1H + f1 * 36 + w0 + 4];
                bl1[0] = smu[O_W1L + f1 * 36 + w0]; bl1[1] = smu[O_W1L + f1 * 36 + w0 + 4];
                MMA16816(d0, AH1[ks], bh0);
                MMA16816(d1, AH1[ks], bh1);
                MMA16816(d0, AL1[ks], bh0);
                MMA16816(d1, AL1[ks], bh1);
                MMA16816(d0, AH1[ks], bl0);
                MMA16816(d1, AH1[ks], bl1);
            }
            // bias + ssp + pack into MLP2 A-frags (k-step np)
            float2 ba = *(const float2*)(b1s + np * 16 + tid * 2);
            float2 bb = *(const float2*)(b1s + np * 16 + 8 + tid * 2);
            float h00 = ssp(d0[0] + ba.x), h01 = ssp(d0[1] + ba.y);
            float h02 = ssp(d0[2] + ba.x), h03 = ssp(d0[3] + ba.y);
            float h10 = ssp(d1[0] + bb.x), h11 = ssp(d1[1] + bb.y);
            float h12 = ssp(d1[2] + bb.x), h13 = ssp(d1[3] + bb.y);
            AH2[np][0] = pk_bf(h00, h01); AL2[np][0] = pk_bf(bfr(h00), bfr(h01));
            AH2[np][1] = pk_bf(h02, h03); AL2[np][1] = pk_bf(bfr(h02), bfr(h03));
            AH2[np][2] = pk_bf(h10, h11); AL2[np][2] = pk_bf(bfr(h10), bfr(h11));
            AH2[np][3] = pk_bf(h12, h13); AL2[np][3] = pk_bf(bfr(h12), bfr(h13));
        }

        // ---- MLP2 + epilogue, h[src] gather pipelined one n-pair ahead ----
        int   dst0 = s_dst[gr],     dst8 = s_dst[gr + 8];
        float C0   = s_C[gr],       C8   = s_C[gr + 8];
        const float* hb0 = g_h + (size_t)s_src[gr] * 128;
        const float* hb8 = g_h + (size_t)s_src[gr + 8] * 128;

        float2 h00 = *(const float2*)(hb0 + tid * 2);
        float2 h01 = *(const float2*)(hb0 + 8 + tid * 2);
        float2 h80 = *(const float2*)(hb8 + tid * 2);
        float2 h81 = *(const float2*)(hb8 + 8 + tid * 2);

#pragma unroll
        for (int np = 0; np < 8; np++) {
            float d0[4] = {0, 0, 0, 0}, d1[4] = {0, 0, 0, 0};
            // prefetch next n-pair's h values
            float2 nh00, nh01, nh80, nh81;
            if (np < 7) {
                int fo = (np + 1) * 16 + tid * 2;
                nh00 = *(const float2*)(hb0 + fo);
                nh01 = *(const float2*)(hb0 + fo + 8);
                nh80 = *(const float2*)(hb8 + fo);
                nh81 = *(const float2*)(hb8 + fo + 8);
            }
            int f0 = np * 16 + gr;            // W2 row for n-tile 2np
            int f1 = f0 + 8;
#pragma unroll
            for (int ks = 0; ks < 8; ks++) {
                u32 bh0[2], bl0[2], bh1[2], bl1[2];
                int w0 = ks * 8 + tid;
                bh0[0] = smu[O_W2H + f0 * 68 + w0]; bh0[1] = smu[O_W2H + f0 * 68 + w0 + 4];
                bl0[0] = smu[O_W2L + f0 * 68 + w0]; bl0[1] = smu[O_W2L + f0 * 68 + w0 + 4];
                bh1[0] = smu[O_W2H + f1 * 68 + w0]; bh1[1] = smu[O_W2H + f1 * 68 + w0 + 4];
                bl1[0] = smu[O_W2L + f1 * 68 + w0]; bl1[1] = smu[O_W2L + f1 * 68 + w0 + 4];
                MMA16816(d0, AH2[ks], bh0);
                MMA16816(d1, AH2[ks], bh1);
                MMA16816(d0, AL2[ks], bh0);
                MMA16816(d1, AL2[ks], bh1);
                MMA16816(d0, AH2[ks], bl0);
                MMA16816(d1, AH2[ks], bl1);
            }
            // epilogue: (D2+b2) * C * h[src] -> red.global.add.v2
            float2 ba = *(const float2*)(b2s + np * 16 + tid * 2);
            float2 bb = *(const float2*)(b2s + np * 16 + 8 + tid * 2);
            if (dst0 >= 0) {
                float* base = g_agg + (size_t)dst0 * 128 + np * 16 + tid * 2;
                float m0 = (d0[0] + ba.x) * C0 * h00.x;
                float m1 = (d0[1] + ba.y) * C0 * h00.y;
                asm volatile("red.global.add.v2.f32 [%0], {%1, %2};"
                             :: "l"(base), "f"(m0), "f"(m1) : "memory");
                float m2 = (d1[0] + bb.x) * C0 * h01.x;
                float m3 = (d1[1] + bb.y) * C0 * h01.y;
                asm volatile("red.global.add.v2.f32 [%0], {%1, %2};"
                             :: "l"(base + 8), "f"(m2), "f"(m3) : "memory");
            }
            if (dst8 >= 0) {
                float* base = g_agg + (size_t)dst8 * 128 + np * 16 + tid * 2;
                float m0 = (d0[2] + ba.x) * C8 * h80.x;
                float m1 = (d0[3] + ba.y) * C8 * h80.y;
                asm volatile("red.global.add.v2.f32 [%0], {%1, %2};"
                             :: "l"(base), "f"(m0), "f"(m1) : "memory");
                float m2 = (d1[2] + bb.x) * C8 * h81.x;
                float m3 = (d1[3] + bb.y) * C8 * h81.y;
                asm volatile("red.global.add.v2.f32 [%0], {%1, %2};"
                             :: "l"(base + 8), "f"(m2), "f"(m3) : "memory");
            }
            h00 = nh00; h01 = nh01; h80 = nh80; h81 = nh81;
        }
        __syncwarp();
    }
}

// ---------------------------------------------------------------- output
__global__ void __launch_bounds__(128) out_kernel(
    const float* __restrict__ w2, const float* __restrict__ b2,
    const float* __restrict__ w3, const float* __restrict__ b3,
    float* __restrict__ out)
{
    extern __shared__ float sm[];
    float* W2t = sm;
    float* W3t = W2t + 16384;
    float* as  = W3t + 16384;
    float* tss = as + 512;
    int t = threadIdx.x;
    for (int i = t; i < 16384; i += 128) {
        int f = i >> 7, k = i & 127;
        W2t[k * 128 + f] = w2[i];
        W3t[k * 128 + f] = w3[i];
    }
    float bb2 = b2[t], bb3 = b3[t];
    __syncthreads();
    int row0 = blockIdx.x * 128;
    for (int rg = 0; rg < 128; rg += 4) {
        int r = row0 + rg;
#pragma unroll
        for (int j = 0; j < 4; j++) {
            int rr = r + j;
            as[j * 128 + t] = (rr < N_NODES) ? g_agg[rr * 128 + t] : 0.0f;
        }
        __syncthreads();
        float a0 = 0, a1 = 0, a2 = 0, a3 = 0;
#pragma unroll 8
        for (int k = 0; k < 128; k++) {
            float wv = W2t[k * 128 + t];
            a0 += as[k] * wv;
            a1 += as[128 + k] * wv;
            a2 += as[256 + k] * wv;
            a3 += as[384 + k] * wv;
        }
        tss[0 * 128 + t] = ssp(a0 + bb2);
        tss[1 * 128 + t] = ssp(a1 + bb2);
        tss[2 * 128 + t] = ssp(a2 + bb2);
        tss[3 * 128 + t] = ssp(a3 + bb2);
        __syncthreads();
        float c0 = 0, c1 = 0, c2 = 0, c3 = 0;
#pragma unroll 8
        for (int k = 0; k < 128; k++) {
            float wv = W3t[k * 128 + t];
            c0 += tss[k] * wv;
            c1 += tss[128 + k] * wv;
            c2 += tss[256 + k] * wv;
            c3 += tss[384 + k] * wv;
        }
        if (r + 0 < N_NODES) out[(r + 0) * 128 + t] = c0 + bb3;
        if (r + 1 < N_NODES) out[(r + 1) * 128 + t] = c1 + bb3;
        if (r + 2 < N_NODES) out[(r + 2) * 128 + t] = c2 + bb3;
        if (r + 3 < N_NODES) out[(r + 3) * 128 + t] = c3 + bb3;
        __syncthreads();
    }
}

// ---------------------------------------------------------------- cleanup
__global__ void cleanup_kernel() {
    int idx = blockIdx.x * blockDim.x + threadIdx.x;
    int stride = gridDim.x * blockDim.x;
    for (int i = idx; i < N_NODES * N_FILT; i += stride) g_agg[i] = 0.0f;
    if (idx < N_COLORS) g_cnt[idx] = 0;
}

// ---------------------------------------------------------------- launch
#define SCL_SMEM  ((16384 + 1024) * 4)
#define OUT_SMEM  ((16384 * 2 + 512 + 512) * 4)

extern "C" void kernel_launch(void* const* d_in, const int* in_sizes, int n_in,
                              void* d_out, int out_size) {
    const float* x    = (const float*)d_in[0];
    const int*   ei   = (const int*)d_in[1];
    const float* ew   = (const float*)d_in[2];
    const float* attr = (const float*)d_in[3];
    const int*   col  = (const int*)d_in[4];
    const float* m1w  = (const float*)d_in[5];
    const float* m1b  = (const float*)d_in[6];
    const float* m2w  = (const float*)d_in[7];
    const float* m2b  = (const float*)d_in[8];
    const float* l1w  = (const float*)d_in[9];
    const float* l2w  = (const float*)d_in[10];
    const float* l2b  = (const float*)d_in[11];
    const float* lw   = (const float*)d_in[12];
    const float* lb   = (const float*)d_in[13];
    float* out = (float*)d_out;

    cudaFuncSetAttribute(edge_kernel, cudaFuncAttributeMaxDynamicSharedMemorySize, EDGE_SMEM);
    cudaFuncSetAttribute(scatter_lin1_kernel, cudaFuncAttributeMaxDynamicSharedMemorySize, SCL_SMEM);
    cudaFuncSetAttribute(out_kernel,  cudaFuncAttributeMaxDynamicSharedMemorySize, OUT_SMEM);

    hist_kernel<<<512, 256>>>(col);
    offset_kernel<<<1, 1>>>();
    scatter_lin1_kernel<<<SC_NB + L1_NB, 256, SCL_SMEM>>>(col, x, l1w);
    edge_kernel<<<NCHUNK, 256, EDGE_SMEM>>>(ei, ew, attr, col, m1w, m1b, m2w, m2b);
    out_kernel<<<L1_NB, 128, OUT_SMEM>>>(l2w, l2b, lw, lb, out);
    cleanup_kernel<<<2048, 256>>>();
}

// round 12
// speedup vs baseline: 1.6933x; 1.6933x over previous
#include <cuda_runtime.h>
#include <cuda_bf16.h>
#include <cstdint>

#define N_NODES 50000
#define N_EDGES 1000000
#define HIDDEN  128
#define N_GAUSS 50
#define N_FILT  128
#define N_COLORS 4
#define CUTOFF_R 10.0f
#define LOG2F_  0.6931471805599453f
#define PI_F    3.14159265358979323846f

#define CH 1024              // edges per block-chunk (color-aligned)
#define NCHUNK 981
#define PERM_SZ (NCHUNK*CH)
#define SC_BS 4096
#define SC_NB 245
#define L1_NB 391
#define FULLM 0xffffffffu

// ---- scratch (static device globals; zero-initialized at module load) ----
__device__ float g_h[N_NODES * HIDDEN];
__device__ float g_agg[N_NODES * N_FILT];
__device__ int   g_perm[PERM_SZ];           // color-sorted (edge id + 1), 0 = pad
__device__ int   g_cnt[N_COLORS];
__device__ int   g_cur[N_COLORS];

__device__ __forceinline__ float ssp(float v) {
    return fmaxf(v, 0.0f) + __logf(1.0f + __expf(-fabsf(v))) - LOG2F_;
}

typedef uint32_t u32;

// pack two f32 -> bf16x2 {lo, hi}
__device__ __forceinline__ u32 pk_bf(float lo, float hi) {
    u32 r;
    asm("cvt.rn.bf16x2.f32 %0, %1, %2;" : "=r"(r) : "f"(hi), "f"(lo));
    return r;
}
__device__ __forceinline__ float bfr(float v) {   // residual after bf16 truncation
    return v - __bfloat162float(__float2bfloat16(v));
}

// m16n8k16 row.col f32.bf16.bf16.f32
#define MMA16816(d, a, b) \
    asm volatile("mma.sync.aligned.m16n8k16.row.col.f32.bf16.bf16.f32 " \
        "{%0,%1,%2,%3}, {%4,%5,%6,%7}, {%8,%9}, {%0,%1,%2,%3};" \
        : "+f"((d)[0]), "+f"((d)[1]), "+f"((d)[2]), "+f"((d)[3]) \
        : "r"((a)[0]), "r"((a)[1]), "r"((a)[2]), "r"((a)[3]), \
          "r"((b)[0]), "r"((b)[1]))

// ---------------------------------------------------------------- histogram
__global__ void hist_kernel(const int* __restrict__ colors) {
    __shared__ int sh[N_COLORS];
    if (threadIdx.x < N_COLORS) sh[threadIdx.x] = 0;
    __syncthreads();
    int idx = blockIdx.x * blockDim.x + threadIdx.x;
    int stride = gridDim.x * blockDim.x;
    for (int i = idx; i < N_EDGES; i += stride) atomicAdd(&sh[colors[i]], 1);
    __syncthreads();
    if (threadIdx.x < N_COLORS) atomicAdd(&g_cnt[threadIdx.x], sh[threadIdx.x]);
}

// ---------------------------------------------------------------- offsets
__global__ void offset_kernel() {
    if (blockIdx.x == 0 && threadIdx.x == 0) {
        int b = 0;
        for (int c = 0; c < N_COLORS; c++) {
            g_cur[c] = b;
            b += (g_cnt[c] + CH - 1) / CH * CH;
        }
    }
}

// ---------------------------------------------------------------- scatter + lin1 (fused)
__global__ void __launch_bounds__(256) scatter_lin1_kernel(
    const int* __restrict__ colors,
    const float* __restrict__ x,
    const float* __restrict__ w)
{
    extern __shared__ float smf[];
    if (blockIdx.x < SC_NB) {
        __shared__ int s_cnt[N_COLORS], s_base[N_COLORS];
        int t = threadIdx.x;
        if (t < N_COLORS) s_cnt[t] = 0;
        __syncthreads();
        int start = blockIdx.x * SC_BS;
        int end = min(start + SC_BS, N_EDGES);
        for (int i = start + t; i < end; i += blockDim.x) atomicAdd(&s_cnt[colors[i]], 1);
        __syncthreads();
        if (t < N_COLORS) { s_base[t] = atomicAdd(&g_cur[t], s_cnt[t]); s_cnt[t] = 0; }
        __syncthreads();
        for (int i = start + t; i < end; i += blockDim.x) {
            int c = colors[i];
            int pos = s_base[c] + atomicAdd(&s_cnt[c], 1);
            g_perm[pos] = i + 1;
        }
    } else {
        int tile = blockIdx.x - SC_NB;
        float* Wt = smf;
        float* xs = Wt + 16384;
        int t = threadIdx.x;
        int th = t & 127, half = t >> 7;
        for (int i = t; i < 16384; i += 256) {
            int f = i >> 7, k = i & 127;
            Wt[k * 128 + f] = w[i];
        }
        __syncthreads();
        int row0 = tile * 128;
        for (int rg = 0; rg < 128; rg += 8) {
            int r = row0 + rg + half * 4;
#pragma unroll
            for (int j = 0; j < 4; j++) {
                int rr = r + j;
                xs[(half * 4 + j) * 128 + th] = (rr < N_NODES) ? x[rr * 128 + th] : 0.0f;
            }
            __syncthreads();
            float a0 = 0, a1 = 0, a2 = 0, a3 = 0;
#pragma unroll 8
            for (int k = 0; k < 128; k++) {
                float wv = Wt[k * 128 + th];
                a0 += xs[(half * 4 + 0) * 128 + k] * wv;
                a1 += xs[(half * 4 + 1) * 128 + k] * wv;
                a2 += xs[(half * 4 + 2) * 128 + k] * wv;
                a3 += xs[(half * 4 + 3) * 128 + k] * wv;
            }
            if (r + 0 < N_NODES) g_h[(r + 0) * 128 + th] = a0;
            if (r + 1 < N_NODES) g_h[(r + 1) * 128 + th] = a1;
            if (r + 2 < N_NODES) g_h[(r + 2) * 128 + th] = a2;
            if (r + 3 < N_NODES) g_h[(r + 3) * 128 + th] = a3;
            __syncthreads();
        }
    }
}

// ---------------------------------------------------------------- HMMA fused edge kernel
// 256 threads = 8 warps; each warp owns 128 edges, 16 per iteration.
// bf16 hi/lo 3-term compensated mma; split accumulator chains for ILP.
// attr A-fragments load DIRECTLY from gmem (no SMEM bounce) -> 107KB SMEM -> 2 CTAs/SM.
//
// SMEM (u32 words):
#define O_W1H  0            // [128 f][36]  (32 k-pair words used)
#define O_W1L  4608
#define O_W2H  9216         // [128 f][68]  (64 words used)
#define O_W2L  17920
#define O_B1   26624        // 128 f32
#define O_B2   26752        // 128 f32
#define O_META 26880        // 8 warps * 64: p[16] src[16] dst[16] C[16]
#define EDGE_SMEM ((26880 + 512) * 4)

__global__ void __launch_bounds__(256, 2) edge_kernel(
    const int* __restrict__ edge_index,
    const float* __restrict__ ew,
    const float* __restrict__ attr,
    const int* __restrict__ colors,
    const float* __restrict__ m1w, const float* __restrict__ m1b,
    const float* __restrict__ m2w, const float* __restrict__ m2b)
{
    extern __shared__ u32 smu[];
    int t = threadIdx.x;
    int chunk0 = blockIdx.x * CH;
    int p0c = g_perm[chunk0] - 1;
    if (p0c < 0) return;                      // gap chunk (block-uniform)
    int c = colors[p0c];

    // ---- weight prep: bf16 hi/lo split into SMEM ----
    {
        const float* w1 = m1w + (size_t)c * 128 * N_GAUSS;
        for (int i = t; i < 128 * 32; i += 256) {
            int f = i >> 5, w = i & 31;
            int k0 = w * 2, k1 = w * 2 + 1;
            float v0 = (k0 < N_GAUSS) ? w1[f * N_GAUSS + k0] : 0.0f;
            float v1 = (k1 < N_GAUSS) ? w1[f * N_GAUSS + k1] : 0.0f;
            smu[O_W1H + f * 36 + w] = pk_bf(v0, v1);
            smu[O_W1L + f * 36 + w] = pk_bf(bfr(v0), bfr(v1));
        }
        const float* w2 = m2w + (size_t)c * 128 * 128;
        for (int i = t; i < 128 * 64; i += 256) {
            int f = i >> 6, w = i & 63;
            float2 v = *(const float2*)(w2 + f * 128 + w * 2);
            smu[O_W2H + f * 68 + w] = pk_bf(v.x, v.y);
            smu[O_W2L + f * 68 + w] = pk_bf(bfr(v.x), bfr(v.y));
        }
        if (t < 128) {
            ((float*)smu)[O_B1 + t] = m1b[c * 128 + t];
            ((float*)smu)[O_B2 + t] = m2b[c * 128 + t];
        }
    }
    __syncthreads();

    int wid = t >> 5, lane = t & 31;
    int gr = lane >> 2, tid = lane & 3;       // mma group-row / thread-in-group
    int*   s_p    = (int*)(smu + O_META + wid * 64);
    int*   s_src  = s_p + 16;
    int*   s_dst  = s_p + 32;
    float* s_C    = (float*)(s_p + 48);
    const float* b1s = (const float*)(smu + O_B1);
    const float* b2s = (const float*)(smu + O_B2);

    for (int it = 0; it < 8; it++) {
        int ebase = chunk0 + wid * 128 + it * 16;

        // ---- metadata (lanes 0..15) ----
        if (lane < 16) {
            int p = g_perm[ebase + lane] - 1;
            int sr = 0, ds = -1;
            float C = 0.0f;
            if (p >= 0) {
                sr = edge_index[p];
                ds = edge_index[N_EDGES + p];
                C = 0.5f * (__cosf(ew[p] * (PI_F / CUTOFF_R)) + 1.0f);
            }
            s_p[lane] = p; s_src[lane] = sr; s_dst[lane] = ds; s_C[lane] = C;
        }
        __syncwarp();

        // ---- attr A-fragments straight from gmem (hi/lo), K=64 -> 4 k-steps ----
        int pg = s_p[gr], p8 = s_p[gr + 8];
        const float* ar0 = attr + (size_t)(pg < 0 ? 0 : pg) * N_GAUSS;
        const float* ar8 = attr + (size_t)(p8 < 0 ? 0 : p8) * N_GAUSS;
        u32 AH1[4][4], AL1[4][4];
#pragma unroll
        for (int ks = 0; ks < 4; ks++) {
            int c0 = ks * 16 + tid * 2;
            int c1 = c0 + 8;
            float2 z = make_float2(0.0f, 0.0f);
            float2 v0 = (pg >= 0 && c0 < N_GAUSS) ? *(const float2*)(ar0 + c0) : z;
            float2 v1 = (p8 >= 0 && c0 < N_GAUSS) ? *(const float2*)(ar8 + c0) : z;
            float2 v2 = (pg >= 0 && c1 < N_GAUSS) ? *(const float2*)(ar0 + c1) : z;
            float2 v3 = (p8 >= 0 && c1 < N_GAUSS) ? *(const float2*)(ar8 + c1) : z;
            AH1[ks][0] = pk_bf(v0.x, v0.y); AL1[ks][0] = pk_bf(bfr(v0.x), bfr(v0.y));
            AH1[ks][1] = pk_bf(v1.x, v1.y); AL1[ks][1] = pk_bf(bfr(v1.x), bfr(v1.y));
            AH1[ks][2] = pk_bf(v2.x, v2.y); AL1[ks][2] = pk_bf(bfr(v2.x), bfr(v2.y));
            AH1[ks][3] = pk_bf(v3.x, v3.y); AL1[ks][3] = pk_bf(bfr(v3.x), bfr(v3.y));
        }

        // ---- MLP1: D1 = attr @ W1^T; 2 independent chains per n-tile;
        //      convert directly into MLP2 A-fragments ----
        u32 AH2[8][4], AL2[8][4];
#pragma unroll
        for (int np = 0; np < 8; np++) {
            float da0[4] = {0, 0, 0, 0}, db0[4] = {0, 0, 0, 0};
            float da1[4] = {0, 0, 0, 0}, db1[4] = {0, 0, 0, 0};
            int f0 = (2 * np) * 8 + gr;
            int f1 = f0 + 8;
#pragma unroll
            for (int ks = 0; ks < 4; ks++) {
                u32 bh0[2], bl0[2], bh1[2], bl1[2];
                int w0 = ks * 8 + tid;
                bh0[0] = smu[O_W1H + f0 * 36 + w0]; bh0[1] = smu[O_W1H + f0 * 36 + w0 + 4];
                bl0[0] = smu[O_W1L + f0 * 36 + w0]; bl0[1] = smu[O_W1L + f0 * 36 + w0 + 4];
                bh1[0] = smu[O_W1H + f1 * 36 + w0]; bh1[1] = smu[O_W1H + f1 * 36 + w0 + 4];
                bl1[0] = smu[O_W1L + f1 * 36 + w0]; bl1[1] = smu[O_W1L + f1 * 36 + w0 + 4];
                MMA16816(da0, AH1[ks], bh0);
                MMA16816(da1, AH1[ks], bh1);
                MMA16816(db0, AL1[ks], bh0);
                MMA16816(db1, AL1[ks], bh1);
                MMA16816(db0, AH1[ks], bl0);
                MMA16816(db1, AH1[ks], bl1);
            }
            float2 ba = *(const float2*)(b1s + np * 16 + tid * 2);
            float2 bb = *(const float2*)(b1s + np * 16 + 8 + tid * 2);
            float h00 = ssp(da0[0] + db0[0] + ba.x), h01 = ssp(da0[1] + db0[1] + ba.y);
            float h02 = ssp(da0[2] + db0[2] + ba.x), h03 = ssp(da0[3] + db0[3] + ba.y);
            float h10 = ssp(da1[0] + db1[0] + bb.x), h11 = ssp(da1[1] + db1[1] + bb.y);
            float h12 = ssp(da1[2] + db1[2] + bb.x), h13 = ssp(da1[3] + db1[3] + bb.y);
            AH2[np][0] = pk_bf(h00, h01); AL2[np][0] = pk_bf(bfr(h00), bfr(h01));
            AH2[np][1] = pk_bf(h02, h03); AL2[np][1] = pk_bf(bfr(h02), bfr(h03));
            AH2[np][2] = pk_bf(h10, h11); AL2[np][2] = pk_bf(bfr(h10), bfr(h11));
            AH2[np][3] = pk_bf(h12, h13); AL2[np][3] = pk_bf(bfr(h12), bfr(h13));
        }

        // ---- MLP2 + epilogue, h[src] gather pipelined one n-pair ahead ----
        int   dst0 = s_dst[gr],     dst8 = s_dst[gr + 8];
        float C0   = s_C[gr],       C8   = s_C[gr + 8];
        const float* hb0 = g_h + (size_t)s_src[gr] * 128;
        const float* hb8 = g_h + (size_t)s_src[gr + 8] * 128;

        float2 h00 = *(const float2*)(hb0 + tid * 2);
        float2 h01 = *(const float2*)(hb0 + 8 + tid * 2);
        float2 h80 = *(const float2*)(hb8 + tid * 2);
        float2 h81 = *(const float2*)(hb8 + 8 + tid * 2);

#pragma unroll
        for (int np = 0; np < 8; np++) {
            float da0[4] = {0, 0, 0, 0}, db0[4] = {0, 0, 0, 0}, dc0[4] = {0, 0, 0, 0};
            float da1[4] = {0, 0, 0, 0}, db1[4] = {0, 0, 0, 0}, dc1[4] = {0, 0, 0, 0};
            float2 nh00, nh01, nh80, nh81;
            if (np < 7) {
                int fo = (np + 1) * 16 + tid * 2;
                nh00 = *(const float2*)(hb0 + fo);
                nh01 = *(const float2*)(hb0 + fo + 8);
                nh80 = *(const float2*)(hb8 + fo);
                nh81 = *(const float2*)(hb8 + fo + 8);
            }
            int f0 = np * 16 + gr;
            int f1 = f0 + 8;
#pragma unroll
            for (int ks = 0; ks < 8; ks++) {
                u32 bh0[2], bl0[2], bh1[2], bl1[2];
                int w0 = ks * 8 + tid;
                bh0[0] = smu[O_W2H + f0 * 68 + w0]; bh0[1] = smu[O_W2H + f0 * 68 + w0 + 4];
                bl0[0] = smu[O_W2L + f0 * 68 + w0]; bl0[1] = smu[O_W2L + f0 * 68 + w0 + 4];
                bh1[0] = smu[O_W2H + f1 * 68 + w0]; bh1[1] = smu[O_W2H + f1 * 68 + w0 + 4];
                bl1[0] = smu[O_W2L + f1 * 68 + w0]; bl1[1] = smu[O_W2L + f1 * 68 + w0 + 4];
                MMA16816(da0, AH2[ks], bh0);
                MMA16816(da1, AH2[ks], bh1);
                MMA16816(db0, AL2[ks], bh0);
                MMA16816(db1, AL2[ks], bh1);
                MMA16816(dc0, AH2[ks], bl0);
                MMA16816(dc1, AH2[ks], bl1);
            }
            float2 ba = *(const float2*)(b2s + np * 16 + tid * 2);
            float2 bb = *(const float2*)(b2s + np * 16 + 8 + tid * 2);
            if (dst0 >= 0) {
                float* base = g_agg + (size_t)dst0 * 128 + np * 16 + tid * 2;
                float m0 = (da0[0] + db0[0] + dc0[0] + ba.x) * C0 * h00.x;
                float m1 = (da0[1] + db0[1] + dc0[1] + ba.y) * C0 * h00.y;
                asm volatile("red.global.add.v2.f32 [%0], {%1, %2};"
                             :: "l"(base), "f"(m0), "f"(m1) : "memory");
                float m2 = (da1[0] + db1[0] + dc1[0] + bb.x) * C0 * h01.x;
                float m3 = (da1[1] + db1[1] + dc1[1] + bb.y) * C0 * h01.y;
                asm volatile("red.global.add.v2.f32 [%0], {%1, %2};"
                             :: "l"(base + 8), "f"(m2), "f"(m3) : "memory");
            }
            if (dst8 >= 0) {
                float* base = g_agg + (size_t)dst8 * 128 + np * 16 + tid * 2;
                float m0 = (da0[2] + db0[2] + dc0[2] + ba.x) * C8 * h80.x;
                float m1 = (da0[3] + db0[3] + dc0[3] + ba.y) * C8 * h80.y;
                asm volatile("red.global.add.v2.f32 [%0], {%1, %2};"
                             :: "l"(base), "f"(m0), "f"(m1) : "memory");
                float m2 = (da1[2] + db1[2] + dc1[2] + bb.x) * C8 * h81.x;
                float m3 = (da1[3] + db1[3] + dc1[3] + bb.y) * C8 * h81.y;
                asm volatile("red.global.add.v2.f32 [%0], {%1, %2};"
                             :: "l"(base + 8), "f"(m2), "f"(m3) : "memory");
            }
            h00 = nh00; h01 = nh01; h80 = nh80; h81 = nh81;
        }
        __syncwarp();
    }
}

// ---------------------------------------------------------------- output
__global__ void __launch_bounds__(128) out_kernel(
    const float* __restrict__ w2, const float* __restrict__ b2,
    const float* __restrict__ w3, const float* __restrict__ b3,
    float* __restrict__ out)
{
    extern __shared__ float sm[];
    float* W2t = sm;
    float* W3t = W2t + 16384;
    float* as  = W3t + 16384;
    float* tss = as + 512;
    int t = threadIdx.x;
    for (int i = t; i < 16384; i += 128) {
        int f = i >> 7, k = i & 127;
        W2t[k * 128 + f] = w2[i];
        W3t[k * 128 + f] = w3[i];
    }
    float bb2 = b2[t], bb3 = b3[t];
    __syncthreads();
    int row0 = blockIdx.x * 128;
    for (int rg = 0; rg < 128; rg += 4) {
        int r = row0 + rg;
#pragma unroll
        for (int j = 0; j < 4; j++) {
            int rr = r + j;
            as[j * 128 + t] = (rr < N_NODES) ? g_agg[rr * 128 + t] : 0.0f;
        }
        __syncthreads();
        float a0 = 0, a1 = 0, a2 = 0, a3 = 0;
#pragma unroll 8
        for (int k = 0; k < 128; k++) {
            float wv = W2t[k * 128 + t];
            a0 += as[k] * wv;
            a1 += as[128 + k] * wv;
            a2 += as[256 + k] * wv;
            a3 += as[384 + k] * wv;
        }
        tss[0 * 128 + t] = ssp(a0 + bb2);
        tss[1 * 128 + t] = ssp(a1 + bb2);
        tss[2 * 128 + t] = ssp(a2 + bb2);
        tss[3 * 128 + t] = ssp(a3 + bb2);
        __syncthreads();
        float c0 = 0, c1 = 0, c2 = 0, c3 = 0;
#pragma unroll 8
        for (int k = 0; k < 128; k++) {
            float wv = W3t[k * 128 + t];
            c0 += tss[k] * wv;
            c1 += tss[128 + k] * wv;
            c2 += tss[256 + k] * wv;
            c3 += tss[384 + k] * wv;
        }
        if (r + 0 < N_NODES) out[(r + 0) * 128 + t] = c0 + bb3;
        if (r + 1 < N_NODES) out[(r + 1) * 128 + t] = c1 + bb3;
        if (r + 2 < N_NODES) out[(r + 2) * 128 + t] = c2 + bb3;
        if (r + 3 < N_NODES) out[(r + 3) * 128 + t] = c3 + bb3;
        __syncthreads();
    }
}

// ---------------------------------------------------------------- cleanup
__global__ void cleanup_kernel() {
    int idx = blockIdx.x * blockDim.x + threadIdx.x;
    int stride = gridDim.x * blockDim.x;
    for (int i = idx; i < N_NODES * N_FILT; i += stride) g_agg[i] = 0.0f;
    if (idx < N_COLORS) g_cnt[idx] = 0;
}

// ---------------------------------------------------------------- launch
#define SCL_SMEM  ((16384 + 1024) * 4)
#define OUT_SMEM  ((16384 * 2 + 512 + 512) * 4)

extern "C" void kernel_launch(void* const* d_in, const int* in_sizes, int n_in,
                              void* d_out, int out_size) {
    const float* x    = (const float*)d_in[0];
    const int*   ei   = (const int*)d_in[1];
    const float* ew   = (const float*)d_in[2];
    const float* attr = (const float*)d_in[3];
    const int*   col  = (const int*)d_in[4];
    const float* m1w  = (const float*)d_in[5];
    const float* m1b  = (const float*)d_in[6];
    const float* m2w  = (const float*)d_in[7];
    const float* m2b  = (const float*)d_in[8];
    const float* l1w  = (const float*)d_in[9];
    const float* l2w  = (const float*)d_in[10];
    const float* l2b  = (const float*)d_in[11];
    const float* lw   = (const float*)d_in[12];
    const float* lb   = (const float*)d_in[13];
    float* out = (float*)d_out;

    cudaFuncSetAttribute(edge_kernel, cudaFuncAttributeMaxDynamicSharedMemorySize, EDGE_SMEM);
    cudaFuncSetAttribute(scatter_lin1_kernel, cudaFuncAttributeMaxDynamicSharedMemorySize, SCL_SMEM);
    cudaFuncSetAttribute(out_kernel,  cudaFuncAttributeMaxDynamicSharedMemorySize, OUT_SMEM);

    hist_kernel<<<512, 256>>>(col);
    offset_kernel<<<1, 1>>>();
    scatter_lin1_kernel<<<SC_NB + L1_NB, 256, SCL_SMEM>>>(col, x, l1w);
    edge_kernel<<<NCHUNK, 256, EDGE_SMEM>>>(ei, ew, attr, col, m1w, m1b, m2w, m2b);
    out_kernel<<<L1_NB, 128, OUT_SMEM>>>(l2w, l2b, lw, lb, out);
    cleanup_kernel<<<2048, 256>>>();
}

// round 15
// speedup vs baseline: 2.9899x; 1.7657x over previous
#include <cuda_runtime.h>
#include <cuda_bf16.h>
#include <cstdint>

#define N_NODES 50000
#define N_EDGES 1000000
#define HIDDEN  128
#define N_GAUSS 50
#define N_FILT  128
#define N_COLORS 4
#define CUTOFF_R 10.0f
#define LOG2F_  0.6931471805599453f
#define PI_F    3.14159265358979323846f

#define CH 1024              // edges per block-chunk (color-aligned)
#define NCHUNK 981
#define PERM_SZ (NCHUNK*CH)
#define SC_BS 4096
#define SC_NB 245
#define MM_NB 391            // ceil(N_NODES / 128)
#define FULLM 0xffffffffu

// ---- scratch (static device globals; zero-initialized at module load) ----
__device__ float g_h[N_NODES * HIDDEN];     // lin1 out; later reused for mid
__device__ float g_agg[N_NODES * N_FILT];
__device__ int   g_perm[PERM_SZ];           // color-sorted (edge id + 1), 0 = pad
__device__ int   g_cnt[N_COLORS];
__device__ int   g_cur[N_COLORS];

__device__ __forceinline__ float ssp(float v) {
    return fmaxf(v, 0.0f) + __logf(1.0f + __expf(-fabsf(v))) - LOG2F_;
}

typedef uint32_t u32;

// pack two f32 -> bf16x2 {lo, hi}
__device__ __forceinline__ u32 pk_bf(float lo, float hi) {
    u32 r;
    asm("cvt.rn.bf16x2.f32 %0, %1, %2;" : "=r"(r) : "f"(hi), "f"(lo));
    return r;
}
__device__ __forceinline__ float bfr(float v) {   // residual after bf16 truncation
    return v - __bfloat162float(__float2bfloat16(v));
}

// m16n8k16 row.col f32.bf16.bf16.f32
#define MMA16816(d, a, b) \
    asm volatile("mma.sync.aligned.m16n8k16.row.col.f32.bf16.bf16.f32 " \
        "{%0,%1,%2,%3}, {%4,%5,%6,%7}, {%8,%9}, {%0,%1,%2,%3};" \
        : "+f"((d)[0]), "+f"((d)[1]), "+f"((d)[2]), "+f"((d)[3]) \
        : "r"((a)[0]), "r"((a)[1]), "r"((a)[2]), "r"((a)[3]), \
          "r"((b)[0]), "r"((b)[1]))

// ---------------------------------------------------------------- histogram
__global__ void hist_kernel(const int* __restrict__ colors) {
    __shared__ int sh[N_COLORS];
    if (threadIdx.x < N_COLORS) sh[threadIdx.x] = 0;
    __syncthreads();
    int idx = blockIdx.x * blockDim.x + threadIdx.x;
    int stride = gridDim.x * blockDim.x;
    for (int i = idx; i < N_EDGES; i += stride) atomicAdd(&sh[colors[i]], 1);
    __syncthreads();
    if (threadIdx.x < N_COLORS) atomicAdd(&g_cnt[threadIdx.x], sh[threadIdx.x]);
}

// ---------------------------------------------------------------- offsets
__global__ void offset_kernel() {
    if (blockIdx.x == 0 && threadIdx.x == 0) {
        int b = 0;
        for (int c = 0; c < N_COLORS; c++) {
            g_cur[c] = b;
            b += (g_cnt[c] + CH - 1) / CH * CH;
        }
    }
}

// ---------------------------------------------------------------- scatter (counting sort)
__global__ void __launch_bounds__(256) scatter_kernel(const int* __restrict__ colors) {
    __shared__ int s_cnt[N_COLORS], s_base[N_COLORS];
    int t = threadIdx.x;
    if (t < N_COLORS) s_cnt[t] = 0;
    __syncthreads();
    int start = blockIdx.x * SC_BS;
    int end = min(start + SC_BS, N_EDGES);
    for (int i = start + t; i < end; i += blockDim.x) atomicAdd(&s_cnt[colors[i]], 1);
    __syncthreads();
    if (t < N_COLORS) { s_base[t] = atomicAdd(&g_cur[t], s_cnt[t]); s_cnt[t] = 0; }
    __syncthreads();
    for (int i = start + t; i < end; i += blockDim.x) {
        int c = colors[i];
        int pos = s_base[c] + atomicAdd(&s_cnt[c], 1);
        g_perm[pos] = i + 1;
    }
}

// ---------------------------------------------------------------- generic HMMA node GEMM
// out[r,:] = act(A[r,:] @ W^T + bias), 128x128 W, bf16 hi/lo 3-term.
// MODE: 0 = plain, 1 = bias + ssp, 2 = bias only.
// 256 threads = 8 warps x 16 rows; A-frags straight from gmem.
#define MM_SMEM ((17408 + 128) * 4)

template<int MODE>
__global__ void __launch_bounds__(256, 2) mm_kernel(
    const float* __restrict__ A,
    const float* __restrict__ W,
    const float* __restrict__ bias,
    float* __restrict__ out)
{
    extern __shared__ u32 smu[];           // WH [128][68] at 0, WL at 8704, bias f32[128]
    int t = threadIdx.x;
    for (int i = t; i < 128 * 64; i += 256) {
        int f = i >> 6, w = i & 63;
        float2 v = *(const float2*)(W + f * 128 + w * 2);
        smu[f * 68 + w] = pk_bf(v.x, v.y);
        smu[8704 + f * 68 + w] = pk_bf(bfr(v.x), bfr(v.y));
    }
    float* bs = (float*)(smu + 17408);
    if (MODE != 0 && t < 128) bs[t] = bias[t];
    __syncthreads();

    int wid = t >> 5, lane = t & 31;
    int gr = lane >> 2, tid = lane & 3;
    int r0 = blockIdx.x * 128 + wid * 16 + gr;
    int r1 = r0 + 8;
    bool v0r = r0 < N_NODES, v1r = r1 < N_NODES;
    const float* a0 = A + (size_t)(v0r ? r0 : 0) * 128;
    const float* a1 = A + (size_t)(v1r ? r1 : 0) * 128;

    u32 AH[8][4], AL[8][4];
#pragma unroll
    for (int ks = 0; ks < 8; ks++) {
        int c0 = ks * 16 + tid * 2, c1 = c0 + 8;
        float2 z = make_float2(0.0f, 0.0f);
        float2 x0 = v0r ? *(const float2*)(a0 + c0) : z;
        float2 x1 = v1r ? *(const float2*)(a1 + c0) : z;
        float2 x2 = v0r ? *(const float2*)(a0 + c1) : z;
        float2 x3 = v1r ? *(const float2*)(a1 + c1) : z;
        AH[ks][0] = pk_bf(x0.x, x0.y); AL[ks][0] = pk_bf(bfr(x0.x), bfr(x0.y));
        AH[ks][1] = pk_bf(x1.x, x1.y); AL[ks][1] = pk_bf(bfr(x1.x), bfr(x1.y));
        AH[ks][2] = pk_bf(x2.x, x2.y); AL[ks][2] = pk_bf(bfr(x2.x), bfr(x2.y));
        AH[ks][3] = pk_bf(x3.x, x3.y); AL[ks][3] = pk_bf(bfr(x3.x), bfr(x3.y));
    }

#pragma unroll
    for (int np = 0; np < 8; np++) {
        float da0[4] = {0, 0, 0, 0}, db0[4] = {0, 0, 0, 0}, dc0[4] = {0, 0, 0, 0};
        float da1[4] = {0, 0, 0, 0}, db1[4] = {0, 0, 0, 0}, dc1[4] = {0, 0, 0, 0};
        int f0 = np * 16 + gr, f1 = f0 + 8;
#pragma unroll
        for (int ks = 0; ks < 8; ks++) {
            u32 bh0[2], bl0[2], bh1[2], bl1[2];
            int w0 = ks * 8 + tid;
            bh0[0] = smu[f0 * 68 + w0];        bh0[1] = smu[f0 * 68 + w0 + 4];
            bl0[0] = smu[8704 + f0 * 68 + w0]; bl0[1] = smu[8704 + f0 * 68 + w0 + 4];
            bh1[0] = smu[f1 * 68 + w0];        bh1[1] = smu[f1 * 68 + w0 + 4];
            bl1[0] = smu[8704 + f1 * 68 + w0]; bl1[1] = smu[8704 + f1 * 68 + w0 + 4];
            MMA16816(da0, AH[ks], bh0);
            MMA16816(da1, AH[ks], bh1);
            MMA16816(db0, AL[ks], bh0);
            MMA16816(db1, AL[ks], bh1);
            MMA16816(dc0, AH[ks], bl0);
            MMA16816(dc1, AH[ks], bl1);
        }
        float s00 = da0[0] + db0[0] + dc0[0], s01 = da0[1] + db0[1] + dc0[1];
        float s02 = da0[2] + db0[2] + dc0[2], s03 = da0[3] + db0[3] + dc0[3];
        float s10 = da1[0] + db1[0] + dc1[0], s11 = da1[1] + db1[1] + dc1[1];
        float s12 = da1[2] + db1[2] + dc1[2], s13 = da1[3] + db1[3] + dc1[3];
        if (MODE != 0) {
            float2 ba = *(const float2*)(bs + np * 16 + tid * 2);
            float2 bb = *(const float2*)(bs + np * 16 + 8 + tid * 2);
            s00 += ba.x; s01 += ba.y; s02 += ba.x; s03 += ba.y;
            s10 += bb.x; s11 += bb.y; s12 += bb.x; s13 += bb.y;
        }
        if (MODE == 1) {
            s00 = ssp(s00); s01 = ssp(s01); s02 = ssp(s02); s03 = ssp(s03);
            s10 = ssp(s10); s11 = ssp(s11); s12 = ssp(s12); s13 = ssp(s13);
        }
        int col = np * 16 + tid * 2;
        if (v0r) {
            *(float2*)(out + (size_t)r0 * 128 + col) = make_float2(s00, s01);
            *(float2*)(out + (size_t)r0 * 128 + col + 8) = make_float2(s10, s11);
        }
        if (v1r) {
            *(float2*)(out + (size_t)r1 * 128 + col) = make_float2(s02, s03);
            *(float2*)(out + (size_t)r1 * 128 + col + 8) = make_float2(s12, s13);
        }
    }
}

// ---------------------------------------------------------------- HMMA fused edge kernel (unchanged from R11)
#define O_W1H  0
#define O_W1L  4608
#define O_W2H  9216
#define O_W2L  17920
#define O_B1   26624
#define O_B2   26752
#define O_META 26880
#define EDGE_SMEM ((26880 + 512) * 4)

__global__ void __launch_bounds__(256, 2) edge_kernel(
    const int* __restrict__ edge_index,
    const float* __restrict__ ew,
    const float* __restrict__ attr,
    const int* __restrict__ colors,
    const float* __restrict__ m1w, const float* __restrict__ m1b,
    const float* __restrict__ m2w, const float* __restrict__ m2b)
{
    extern __shared__ u32 smu[];
    int t = threadIdx.x;
    int chunk0 = blockIdx.x * CH;
    int p0c = g_perm[chunk0] - 1;
    if (p0c < 0) return;
    int c = colors[p0c];

    {
        const float* w1 = m1w + (size_t)c * 128 * N_GAUSS;
        for (int i = t; i < 128 * 32; i += 256) {
            int f = i >> 5, w = i & 31;
            int k0 = w * 2, k1 = w * 2 + 1;
            float v0 = (k0 < N_GAUSS) ? w1[f * N_GAUSS + k0] : 0.0f;
            float v1 = (k1 < N_GAUSS) ? w1[f * N_GAUSS + k1] : 0.0f;
            smu[O_W1H + f * 36 + w] = pk_bf(v0, v1);
            smu[O_W1L + f * 36 + w] = pk_bf(bfr(v0), bfr(v1));
        }
        const float* w2 = m2w + (size_t)c * 128 * 128;
        for (int i = t; i < 128 * 64; i += 256) {
            int f = i >> 6, w = i & 63;
            float2 v = *(const float2*)(w2 + f * 128 + w * 2);
            smu[O_W2H + f * 68 + w] = pk_bf(v.x, v.y);
            smu[O_W2L + f * 68 + w] = pk_bf(bfr(v.x), bfr(v.y));
        }
        if (t < 128) {
            ((float*)smu)[O_B1 + t] = m1b[c * 128 + t];
            ((float*)smu)[O_B2 + t] = m2b[c * 128 + t];
        }
    }
    __syncthreads();

    int wid = t >> 5, lane = t & 31;
    int gr = lane >> 2, tid = lane & 3;
    int*   s_p    = (int*)(smu + O_META + wid * 64);
    int*   s_src  = s_p + 16;
    int*   s_dst  = s_p + 32;
    float* s_C    = (float*)(s_p + 48);
    const float* b1s = (const float*)(smu + O_B1);
    const float* b2s = (const float*)(smu + O_B2);

    for (int it = 0; it < 8; it++) {
        int ebase = chunk0 + wid * 128 + it * 16;

        if (lane < 16) {
            int p = g_perm[ebase + lane] - 1;
            int sr = 0, ds = -1;
            float C = 0.0f;
            if (p >= 0) {
                sr = edge_index[p];
                ds = edge_index[N_EDGES + p];
                C = 0.5f * (__cosf(ew[p] * (PI_F / CUTOFF_R)) + 1.0f);
            }
            s_p[lane] = p; s_src[lane] = sr; s_dst[lane] = ds; s_C[lane] = C;
        }
        __syncwarp();

        int pg = s_p[gr], p8 = s_p[gr + 8];
        const float* ar0 = attr + (size_t)(pg < 0 ? 0 : pg) * N_GAUSS;
        const float* ar8 = attr + (size_t)(p8 < 0 ? 0 : p8) * N_GAUSS;
        u32 AH1[4][4], AL1[4][4];
#pragma unroll
        for (int ks = 0; ks < 4; ks++) {
            int c0 = ks * 16 + tid * 2;
            int c1 = c0 + 8;
            float2 z = make_float2(0.0f, 0.0f);
            float2 v0 = (pg >= 0 && c0 < N_GAUSS) ? *(const float2*)(ar0 + c0) : z;
            float2 v1 = (p8 >= 0 && c0 < N_GAUSS) ? *(const float2*)(ar8 + c0) : z;
            float2 v2 = (pg >= 0 && c1 < N_GAUSS) ? *(const float2*)(ar0 + c1) : z;
            float2 v3 = (p8 >= 0 && c1 < N_GAUSS) ? *(const float2*)(ar8 + c1) : z;
            AH1[ks][0] = pk_bf(v0.x, v0.y); AL1[ks][0] = pk_bf(bfr(v0.x), bfr(v0.y));
            AH1[ks][1] = pk_bf(v1.x, v1.y); AL1[ks][1] = pk_bf(bfr(v1.x), bfr(v1.y));
            AH1[ks][2] = pk_bf(v2.x, v2.y); AL1[ks][2] = pk_bf(bfr(v2.x), bfr(v2.y));
            AH1[ks][3] = pk_bf(v3.x, v3.y); AL1[ks][3] = pk_bf(bfr(v3.x), bfr(v3.y));
        }

        u32 AH2[8][4], AL2[8][4];
#pragma unroll
        for (int np = 0; np < 8; np++) {
            float da0[4] = {0, 0, 0, 0}, db0[4] = {0, 0, 0, 0};
            float da1[4] = {0, 0, 0, 0}, db1[4] = {0, 0, 0, 0};
            int f0 = (2 * np) * 8 + gr;
            int f1 = f0 + 8;
#pragma unroll
            for (int ks = 0; ks < 4; ks++) {
                u32 bh0[2], bl0[2], bh1[2], bl1[2];
                int w0 = ks * 8 + tid;
                bh0[0] = smu[O_W1H + f0 * 36 + w0]; bh0[1] = smu[O_W1H + f0 * 36 + w0 + 4];
                bl0[0] = smu[O_W1L + f0 * 36 + w0]; bl0[1] = smu[O_W1L + f0 * 36 + w0 + 4];
                bh1[0] = smu[O_W1H + f1 * 36 + w0]; bh1[1] = smu[O_W1H + f1 * 36 + w0 + 4];
                bl1[0] = smu[O_W1L + f1 * 36 + w0]; bl1[1] = smu[O_W1L + f1 * 36 + w0 + 4];
                MMA16816(da0, AH1[ks], bh0);
                MMA16816(da1, AH1[ks], bh1);
                MMA16816(db0, AL1[ks], bh0);
                MMA16816(db1, AL1[ks], bh1);
                MMA16816(db0, AH1[ks], bl0);
                MMA16816(db1, AH1[ks], bl1);
            }
            float2 ba = *(const float2*)(b1s + np * 16 + tid * 2);
            float2 bb = *(const float2*)(b1s + np * 16 + 8 + tid * 2);
            float h00 = ssp(da0[0] + db0[0] + ba.x), h01 = ssp(da0[1] + db0[1] + ba.y);
            float h02 = ssp(da0[2] + db0[2] + ba.x), h03 = ssp(da0[3] + db0[3] + ba.y);
            float h10 = ssp(da1[0] + db1[0] + bb.x), h11 = ssp(da1[1] + db1[1] + bb.y);
            float h12 = ssp(da1[2] + db1[2] + bb.x), h13 = ssp(da1[3] + db1[3] + bb.y);
            AH2[np][0] = pk_bf(h00, h01); AL2[np][0] = pk_bf(bfr(h00), bfr(h01));
            AH2[np][1] = pk_bf(h02, h03); AL2[np][1] = pk_bf(bfr(h02), bfr(h03));
            AH2[np][2] = pk_bf(h10, h11); AL2[np][2] = pk_bf(bfr(h10), bfr(h11));
            AH2[np][3] = pk_bf(h12, h13); AL2[np][3] = pk_bf(bfr(h12), bfr(h13));
        }

        int   dst0 = s_dst[gr],     dst8 = s_dst[gr + 8];
        float C0   = s_C[gr],       C8   = s_C[gr + 8];
        const float* hb0 = g_h + (size_t)s_src[gr] * 128;
        const float* hb8 = g_h + (size_t)s_src[gr + 8] * 128;

        float2 h00 = *(const float2*)(hb0 + tid * 2);
        float2 h01 = *(const float2*)(hb0 + 8 + tid * 2);
        float2 h80 = *(const float2*)(hb8 + tid * 2);
        float2 h81 = *(const float2*)(hb8 + 8 + tid * 2);

#pragma unroll
        for (int np = 0; np < 8; np++) {
            float da0[4] = {0, 0, 0, 0}, db0[4] = {0, 0, 0, 0}, dc0[4] = {0, 0, 0, 0};
            float da1[4] = {0, 0, 0, 0}, db1[4] = {0, 0, 0, 0}, dc1[4] = {0, 0, 0, 0};
            float2 nh00, nh01, nh80, nh81;
            if (np < 7) {
                int fo = (np + 1) * 16 + tid * 2;
                nh00 = *(const float2*)(hb0 + fo);
                nh01 = *(const float2*)(hb0 + fo + 8);
                nh80 = *(const float2*)(hb8 + fo);
                nh81 = *(const float2*)(hb8 + fo + 8);
            }
            int f0 = np * 16 + gr;
            int f1 = f0 + 8;
#pragma unroll
            for (int ks = 0; ks < 8; ks++) {
                u32 bh0[2], bl0[2], bh1[2], bl1[2];
                int w0 = ks * 8 + tid;
                bh0[0] = smu[O_W2H + f0 * 68 + w0]; bh0[1] = smu[O_W2H + f0 * 68 + w0 + 4];
                bl0[0] = smu[O_W2L + f0 * 68 + w0]; bl0[1] = smu[O_W2L + f0 * 68 + w0 + 4];
                bh1[0] = smu[O_W2H + f1 * 68 + w0]; bh1[1] = smu[O_W2H + f1 * 68 + w0 + 4];
                bl1[0] = smu[O_W2L + f1 * 68 + w0]; bl1[1] = smu[O_W2L + f1 * 68 + w0 + 4];
                MMA16816(da0, AH2[ks], bh0);
                MMA16816(da1, AH2[ks], bh1);
                MMA16816(db0, AL2[ks], bh0);
                MMA16816(db1, AL2[ks], bh1);
                MMA16816(dc0, AH2[ks], bl0);
                MMA16816(dc1, AH2[ks], bl1);
            }
            float2 ba = *(const float2*)(b2s + np * 16 + tid * 2);
            float2 bb = *(const float2*)(b2s + np * 16 + 8 + tid * 2);
            if (dst0 >= 0) {
                float* base = g_agg + (size_t)dst0 * 128 + np * 16 + tid * 2;
                float m0 = (da0[0] + db0[0] + dc0[0] + ba.x) * C0 * h00.x;
                float m1 = (da0[1] + db0[1] + dc0[1] + ba.y) * C0 * h00.y;
                asm volatile("red.global.add.v2.f32 [%0], {%1, %2};"
                             :: "l"(base), "f"(m0), "f"(m1) : "memory");
                float m2 = (da1[0] + db1[0] + dc1[0] + bb.x) * C0 * h01.x;
                float m3 = (da1[1] + db1[1] + dc1[1] + bb.y) * C0 * h01.y;
                asm volatile("red.global.add.v2.f32 [%0], {%1, %2};"
                             :: "l"(base + 8), "f"(m2), "f"(m3) : "memory");
            }
            if (dst8 >= 0) {
                float* base = g_agg + (size_t)dst8 * 128 + np * 16 + tid * 2;
                float m0 = (da0[2] + db0[2] + dc0[2] + ba.x) * C8 * h80.x;
                float m1 = (da0[3] + db0[3] + dc0[3] + ba.y) * C8 * h80.y;
                asm volatile("red.global.add.v2.f32 [%0], {%1, %2};"
                             :: "l"(base), "f"(m0), "f"(m1) : "memory");
                float m2 = (da1[2] + db1[2] + dc1[2] + bb.x) * C8 * h81.x;
                float m3 = (da1[3] + db1[3] + dc1[3] + bb.y) * C8 * h81.y;
                asm volatile("red.global.add.v2.f32 [%0], {%1, %2};"
                             :: "l"(base + 8), "f"(m2), "f"(m3) : "memory");
            }
            h00 = nh00; h01 = nh01; h80 = nh80; h81 = nh81;
        }
        __syncwarp();
    }
}

// ---------------------------------------------------------------- cleanup
__global__ void cleanup_kernel() {
    int idx = blockIdx.x * blockDim.x + threadIdx.x;
    int stride = gridDim.x * blockDim.x;
    for (int i = idx; i < N_NODES * N_FILT; i += stride) g_agg[i] = 0.0f;
    if (idx < N_COLORS) g_cnt[idx] = 0;
}

// ---------------------------------------------------------------- launch
extern "C" void kernel_launch(void* const* d_in, const int* in_sizes, int n_in,
                              void* d_out, int out_size) {
    const float* x    = (const float*)d_in[0];
    const int*   ei   = (const int*)d_in[1];
    const float* ew   = (const float*)d_in[2];
    const float* attr = (const float*)d_in[3];
    const int*   col  = (const int*)d_in[4];
    const float* m1w  = (const float*)d_in[5];
    const float* m1b  = (const float*)d_in[6];
    const float* m2w  = (const float*)d_in[7];
    const float* m2b  = (const float*)d_in[8];
    const float* l1w  = (const float*)d_in[9];
    const float* l2w  = (const float*)d_in[10];
    const float* l2b  = (const float*)d_in[11];
    const float* lw   = (const float*)d_in[12];
    const float* lb   = (const float*)d_in[13];
    float* out = (float*)d_out;

    float* gh_ptr;
    float* gagg_ptr;
    cudaGetSymbolAddress((void**)&gh_ptr, g_h);
    cudaGetSymbolAddress((void**)&gagg_ptr, g_agg);

    cudaFuncSetAttribute(edge_kernel, cudaFuncAttributeMaxDynamicSharedMemorySize, EDGE_SMEM);
    cudaFuncSetAttribute(mm_kernel<0>, cudaFuncAttributeMaxDynamicSharedMemorySize, MM_SMEM);
    cudaFuncSetAttribute(mm_kernel<1>, cudaFuncAttributeMaxDynamicSharedMemorySize, MM_SMEM);
    cudaFuncSetAttribute(mm_kernel<2>, cudaFuncAttributeMaxDynamicSharedMemorySize, MM_SMEM);

    hist_kernel<<<512, 256>>>(col);
    offset_kernel<<<1, 1>>>();
    scatter_kernel<<<SC_NB, 256>>>(col);
    mm_kernel<0><<<MM_NB, 256, MM_SMEM>>>(x, l1w, nullptr, gh_ptr);              // lin1
    edge_kernel<<<NCHUNK, 256, EDGE_SMEM>>>(ei, ew, attr, col, m1w, m1b, m2w, m2b);
    mm_kernel<1><<<MM_NB, 256, MM_SMEM>>>(gagg_ptr, l2w, l2b, gh_ptr);           // mid = ssp(agg@W2+b2), reuse g_h
    mm_kernel<2><<<MM_NB, 256, MM_SMEM>>>(gh_ptr, lw, lb, out);                  // out = mid@W3+b3
    cleanup_kernel<<<2048, 256>>>();
}

// round 16
// speedup vs baseline: 4.0426x; 1.3521x over previous
#include <cuda_runtime.h>
#include <cuda_fp16.h>
#include <cstdint>

#define N_NODES 50000
#define N_EDGES 1000000
#define HIDDEN  128
#define N_GAUSS 50
#define N_FILT  128
#define N_COLORS 4
#define CUTOFF_R 10.0f
#define LOG2F_  0.6931471805599453f
#define PI_F    3.14159265358979323846f

#define CH 1024              // edges per block-chunk (color-aligned)
#define NCHUNK 981
#define PERM_SZ (NCHUNK*CH)
#define SC_BS 4096
#define SC_NB 245
#define MM_NB 391            // ceil(N_NODES / 128)
#define FULLM 0xffffffffu

// ---- scratch (static device globals; zero-initialized at module load) ----
__device__ float g_h[N_NODES * HIDDEN];     // lin1 out; later reused for mid
__device__ float g_agg[N_NODES * N_FILT];
__device__ int   g_perm[PERM_SZ];           // color-sorted (edge id + 1), 0 = pad
__device__ int   g_cnt[N_COLORS];
__device__ int   g_cur[N_COLORS];

__device__ __forceinline__ float ssp(float v) {
    return fmaxf(v, 0.0f) + __logf(1.0f + __expf(-fabsf(v))) - LOG2F_;
}

typedef uint32_t u32;

// pack two f32 -> f16x2 {lo, hi}
__device__ __forceinline__ u32 pk_h(float lo, float hi) {
    u32 r;
    asm("cvt.rn.f16x2.f32 %0, %1, %2;" : "=r"(r) : "f"(hi), "f"(lo));
    return r;
}
__device__ __forceinline__ float hr(float v) {   // residual after fp16 truncation
    return v - __half2float(__float2half_rn(v));
}

// m16n8k16 row.col f32.f16.f16.f32
#define MMA16816(d, a, b) \
    asm volatile("mma.sync.aligned.m16n8k16.row.col.f32.f16.f16.f32 " \
        "{%0,%1,%2,%3}, {%4,%5,%6,%7}, {%8,%9}, {%0,%1,%2,%3};" \
        : "+f"((d)[0]), "+f"((d)[1]), "+f"((d)[2]), "+f"((d)[3]) \
        : "r"((a)[0]), "r"((a)[1]), "r"((a)[2]), "r"((a)[3]), \
          "r"((b)[0]), "r"((b)[1]))

// ---------------------------------------------------------------- histogram
__global__ void hist_kernel(const int* __restrict__ colors) {
    __shared__ int sh[N_COLORS];
    if (threadIdx.x < N_COLORS) sh[threadIdx.x] = 0;
    __syncthreads();
    int idx = blockIdx.x * blockDim.x + threadIdx.x;
    int stride = gridDim.x * blockDim.x;
    for (int i = idx; i < N_EDGES; i += stride) atomicAdd(&sh[colors[i]], 1);
    __syncthreads();
    if (threadIdx.x < N_COLORS) atomicAdd(&g_cnt[threadIdx.x], sh[threadIdx.x]);
}

// ---------------------------------------------------------------- offsets
__global__ void offset_kernel() {
    if (blockIdx.x == 0 && threadIdx.x == 0) {
        int b = 0;
        for (int c = 0; c < N_COLORS; c++) {
            g_cur[c] = b;
            b += (g_cnt[c] + CH - 1) / CH * CH;
        }
    }
}

// ---------------------------------------------------------------- scatter (counting sort)
__global__ void __launch_bounds__(256) scatter_kernel(const int* __restrict__ colors) {
    __shared__ int s_cnt[N_COLORS], s_base[N_COLORS];
    int t = threadIdx.x;
    if (t < N_COLORS) s_cnt[t] = 0;
    __syncthreads();
    int start = blockIdx.x * SC_BS;
    int end = min(start + SC_BS, N_EDGES);
    for (int i = start + t; i < end; i += blockDim.x) atomicAdd(&s_cnt[colors[i]], 1);
    __syncthreads();
    if (t < N_COLORS) { s_base[t] = atomicAdd(&g_cur[t], s_cnt[t]); s_cnt[t] = 0; }
    __syncthreads();
    for (int i = start + t; i < end; i += blockDim.x) {
        int c = colors[i];
        int pos = s_base[c] + atomicAdd(&s_cnt[c], 1);
        g_perm[pos] = i + 1;
    }
}

// ---------------------------------------------------------------- generic HMMA node GEMM
// out[r,:] = act(A[r,:] @ W^T + bias); W single fp16, A fp16 hi/lo 2-term.
// MODE: 0 = plain, 1 = bias + ssp, 2 = bias only.
#define MM_SMEM ((8704 + 128) * 4)

template<int MODE>
__global__ void __launch_bounds__(256, 2) mm_kernel(
    const float* __restrict__ A,
    const float* __restrict__ W,
    const float* __restrict__ bias,
    float* __restrict__ out)
{
    extern __shared__ u32 smu[];           // WH [128][68] words; bias f32[128] at 8704
    int t = threadIdx.x;
    for (int i = t; i < 128 * 64; i += 256) {
        int f = i >> 6, w = i & 63;
        float2 v = *(const float2*)(W + f * 128 + w * 2);
        smu[f * 68 + w] = pk_h(v.x, v.y);
    }
    float* bs = (float*)(smu + 8704);
    if (MODE != 0 && t < 128) bs[t] = bias[t];
    __syncthreads();

    int wid = t >> 5, lane = t & 31;
    int gr = lane >> 2, tid = lane & 3;
    int r0 = blockIdx.x * 128 + wid * 16 + gr;
    int r1 = r0 + 8;
    bool v0r = r0 < N_NODES, v1r = r1 < N_NODES;
    const float* a0 = A + (size_t)(v0r ? r0 : 0) * 128;
    const float* a1 = A + (size_t)(v1r ? r1 : 0) * 128;

    u32 AH[8][4], AL[8][4];
#pragma unroll
    for (int ks = 0; ks < 8; ks++) {
        int c0 = ks * 16 + tid * 2, c1 = c0 + 8;
        float2 z = make_float2(0.0f, 0.0f);
        float2 x0 = v0r ? *(const float2*)(a0 + c0) : z;
        float2 x1 = v1r ? *(const float2*)(a1 + c0) : z;
        float2 x2 = v0r ? *(const float2*)(a0 + c1) : z;
        float2 x3 = v1r ? *(const float2*)(a1 + c1) : z;
        AH[ks][0] = pk_h(x0.x, x0.y); AL[ks][0] = pk_h(hr(x0.x), hr(x0.y));
        AH[ks][1] = pk_h(x1.x, x1.y); AL[ks][1] = pk_h(hr(x1.x), hr(x1.y));
        AH[ks][2] = pk_h(x2.x, x2.y); AL[ks][2] = pk_h(hr(x2.x), hr(x2.y));
        AH[ks][3] = pk_h(x3.x, x3.y); AL[ks][3] = pk_h(hr(x3.x), hr(x3.y));
    }

#pragma unroll
    for (int np = 0; np < 8; np++) {
        float da0[4] = {0, 0, 0, 0}, db0[4] = {0, 0, 0, 0};
        float da1[4] = {0, 0, 0, 0}, db1[4] = {0, 0, 0, 0};
        int f0 = np * 16 + gr, f1 = f0 + 8;
#pragma unroll
        for (int ks = 0; ks < 8; ks++) {
            u32 bh0[2], bh1[2];
            int w0 = ks * 8 + tid;
            bh0[0] = smu[f0 * 68 + w0]; bh0[1] = smu[f0 * 68 + w0 + 4];
            bh1[0] = smu[f1 * 68 + w0]; bh1[1] = smu[f1 * 68 + w0 + 4];
            MMA16816(da0, AH[ks], bh0);
            MMA16816(da1, AH[ks], bh1);
            MMA16816(db0, AL[ks], bh0);
            MMA16816(db1, AL[ks], bh1);
        }
        float s00 = da0[0] + db0[0], s01 = da0[1] + db0[1];
        float s02 = da0[2] + db0[2], s03 = da0[3] + db0[3];
        float s10 = da1[0] + db1[0], s11 = da1[1] + db1[1];
        float s12 = da1[2] + db1[2], s13 = da1[3] + db1[3];
        if (MODE != 0) {
            float2 ba = *(const float2*)(bs + np * 16 + tid * 2);
            float2 bb = *(const float2*)(bs + np * 16 + 8 + tid * 2);
            s00 += ba.x; s01 += ba.y; s02 += ba.x; s03 += ba.y;
            s10 += bb.x; s11 += bb.y; s12 += bb.x; s13 += bb.y;
        }
        if (MODE == 1) {
            s00 = ssp(s00); s01 = ssp(s01); s02 = ssp(s02); s03 = ssp(s03);
            s10 = ssp(s10); s11 = ssp(s11); s12 = ssp(s12); s13 = ssp(s13);
        }
        int col = np * 16 + tid * 2;
        if (v0r) {
            *(float2*)(out + (size_t)r0 * 128 + col) = make_float2(s00, s01);
            *(float2*)(out + (size_t)r0 * 128 + col + 8) = make_float2(s10, s11);
        }
        if (v1r) {
            *(float2*)(out + (size_t)r1 * 128 + col) = make_float2(s02, s03);
            *(float2*)(out + (size_t)r1 * 128 + col + 8) = make_float2(s12, s13);
        }
    }
}

// ---------------------------------------------------------------- HMMA fused edge kernel
// fp16 2-term: W single fp16, A (attr/hidden) fp16 hi/lo.
// SMEM (u32 words): W1 [128][36] | W2 [128][68] | b1 | b2 | meta
#define O_W1   0
#define O_W2   4608
#define O_B1   13312
#define O_B2   13440
#define O_META 13568
#define EDGE_SMEM ((13568 + 512) * 4)

__global__ void __launch_bounds__(256, 2) edge_kernel(
    const int* __restrict__ edge_index,
    const float* __restrict__ ew,
    const float* __restrict__ attr,
    const int* __restrict__ colors,
    const float* __restrict__ m1w, const float* __restrict__ m1b,
    const float* __restrict__ m2w, const float* __restrict__ m2b)
{
    extern __shared__ u32 smu[];
    int t = threadIdx.x;
    int chunk0 = blockIdx.x * CH;
    int p0c = g_perm[chunk0] - 1;
    if (p0c < 0) return;
    int c = colors[p0c];

    {
        const float* w1 = m1w + (size_t)c * 128 * N_GAUSS;
        for (int i = t; i < 128 * 32; i += 256) {
            int f = i >> 5, w = i & 31;
            int k0 = w * 2, k1 = w * 2 + 1;
            float v0 = (k0 < N_GAUSS) ? w1[f * N_GAUSS + k0] : 0.0f;
            float v1 = (k1 < N_GAUSS) ? w1[f * N_GAUSS + k1] : 0.0f;
            smu[O_W1 + f * 36 + w] = pk_h(v0, v1);
        }
        const float* w2 = m2w + (size_t)c * 128 * 128;
        for (int i = t; i < 128 * 64; i += 256) {
            int f = i >> 6, w = i & 63;
            float2 v = *(const float2*)(w2 + f * 128 + w * 2);
            smu[O_W2 + f * 68 + w] = pk_h(v.x, v.y);
        }
        if (t < 128) {
            ((float*)smu)[O_B1 + t] = m1b[c * 128 + t];
            ((float*)smu)[O_B2 + t] = m2b[c * 128 + t];
        }
    }
    __syncthreads();

    int wid = t >> 5, lane = t & 31;
    int gr = lane >> 2, tid = lane & 3;
    int*   s_p    = (int*)(smu + O_META + wid * 64);
    int*   s_src  = s_p + 16;
    int*   s_dst  = s_p + 32;
    float* s_C    = (float*)(s_p + 48);
    const float* b1s = (const float*)(smu + O_B1);
    const float* b2s = (const float*)(smu + O_B2);

    for (int it = 0; it < 8; it++) {
        int ebase = chunk0 + wid * 128 + it * 16;

        if (lane < 16) {
            int p = g_perm[ebase + lane] - 1;
            int sr = 0, ds = -1;
            float C = 0.0f;
            if (p >= 0) {
                sr = edge_index[p];
                ds = edge_index[N_EDGES + p];
                C = 0.5f * (__cosf(ew[p] * (PI_F / CUTOFF_R)) + 1.0f);
            }
            s_p[lane] = p; s_src[lane] = sr; s_dst[lane] = ds; s_C[lane] = C;
        }
        __syncwarp();

        // ---- attr A-fragments from gmem (fp16 hi/lo), K=64 -> 4 k-steps ----
        int pg = s_p[gr], p8 = s_p[gr + 8];
        const float* ar0 = attr + (size_t)(pg < 0 ? 0 : pg) * N_GAUSS;
        const float* ar8 = attr + (size_t)(p8 < 0 ? 0 : p8) * N_GAUSS;
        u32 AH1[4][4], AL1[4][4];
#pragma unroll
        for (int ks = 0; ks < 4; ks++) {
            int c0 = ks * 16 + tid * 2;
            int c1 = c0 + 8;
            float2 z = make_float2(0.0f, 0.0f);
            float2 v0 = (pg >= 0 && c0 < N_GAUSS) ? *(const float2*)(ar0 + c0) : z;
            float2 v1 = (p8 >= 0 && c0 < N_GAUSS) ? *(const float2*)(ar8 + c0) : z;
            float2 v2 = (pg >= 0 && c1 < N_GAUSS) ? *(const float2*)(ar0 + c1) : z;
            float2 v3 = (p8 >= 0 && c1 < N_GAUSS) ? *(const float2*)(ar8 + c1) : z;
            AH1[ks][0] = pk_h(v0.x, v0.y); AL1[ks][0] = pk_h(hr(v0.x), hr(v0.y));
            AH1[ks][1] = pk_h(v1.x, v1.y); AL1[ks][1] = pk_h(hr(v1.x), hr(v1.y));
            AH1[ks][2] = pk_h(v2.x, v2.y); AL1[ks][2] = pk_h(hr(v2.x), hr(v2.y));
            AH1[ks][3] = pk_h(v3.x, v3.y); AL1[ks][3] = pk_h(hr(v3.x), hr(v3.y));
        }

        // ---- MLP1: 2 chains per n-tile; convert directly into MLP2 A-frags ----
        u32 AH2[8][4], AL2[8][4];
#pragma unroll
        for (int np = 0; np < 8; np++) {
            float da0[4] = {0, 0, 0, 0}, db0[4] = {0, 0, 0, 0};
            float da1[4] = {0, 0, 0, 0}, db1[4] = {0, 0, 0, 0};
            int f0 = (2 * np) * 8 + gr;
            int f1 = f0 + 8;
#pragma unroll
            for (int ks = 0; ks < 4; ks++) {
                u32 bh0[2], bh1[2];
                int w0 = ks * 8 + tid;
                bh0[0] = smu[O_W1 + f0 * 36 + w0]; bh0[1] = smu[O_W1 + f0 * 36 + w0 + 4];
                bh1[0] = smu[O_W1 + f1 * 36 + w0]; bh1[1] = smu[O_W1 + f1 * 36 + w0 + 4];
                MMA16816(da0, AH1[ks], bh0);
                MMA16816(da1, AH1[ks], bh1);
                MMA16816(db0, AL1[ks], bh0);
                MMA16816(db1, AL1[ks], bh1);
            }
            float2 ba = *(const float2*)(b1s + np * 16 + tid * 2);
            float2 bb = *(const float2*)(b1s + np * 16 + 8 + tid * 2);
            float h00 = ssp(da0[0] + db0[0] + ba.x), h01 = ssp(da0[1] + db0[1] + ba.y);
            float h02 = ssp(da0[2] + db0[2] + ba.x), h03 = ssp(da0[3] + db0[3] + ba.y);
            float h10 = ssp(da1[0] + db1[0] + bb.x), h11 = ssp(da1[1] + db1[1] + bb.y);
            float h12 = ssp(da1[2] + db1[2] + bb.x), h13 = ssp(da1[3] + db1[3] + bb.y);
            AH2[np][0] = pk_h(h00, h01); AL2[np][0] = pk_h(hr(h00), hr(h01));
            AH2[np][1] = pk_h(h02, h03); AL2[np][1] = pk_h(hr(h02), hr(h03));
            AH2[np][2] = pk_h(h10, h11); AL2[np][2] = pk_h(hr(h10), hr(h11));
            AH2[np][3] = pk_h(h12, h13); AL2[np][3] = pk_h(hr(h12), hr(h13));
        }

        // ---- MLP2 + epilogue, h[src] gather pipelined one n-pair ahead ----
        int   dst0 = s_dst[gr],     dst8 = s_dst[gr + 8];
        float C0   = s_C[gr],       C8   = s_C[gr + 8];
        const float* hb0 = g_h + (size_t)s_src[gr] * 128;
        const float* hb8 = g_h + (size_t)s_src[gr + 8] * 128;

        float2 h00 = *(const float2*)(hb0 + tid * 2);
        float2 h01 = *(const float2*)(hb0 + 8 + tid * 2);
        float2 h80 = *(const float2*)(hb8 + tid * 2);
        float2 h81 = *(const float2*)(hb8 + 8 + tid * 2);

#pragma unroll
        for (int np = 0; np < 8; np++) {
            float da0[4] = {0, 0, 0, 0}, db0[4] = {0, 0, 0, 0};
            float da1[4] = {0, 0, 0, 0}, db1[4] = {0, 0, 0, 0};
            float2 nh00, nh01, nh80, nh81;
            if (np < 7) {
                int fo = (np + 1) * 16 + tid * 2;
                nh00 = *(const float2*)(hb0 + fo);
                nh01 = *(const float2*)(hb0 + fo + 8);
                nh80 = *(const float2*)(hb8 + fo);
                nh81 = *(const float2*)(hb8 + fo + 8);
            }
            int f0 = np * 16 + gr;
            int f1 = f0 + 8;
#pragma unroll
            for (int ks = 0; ks < 8; ks++) {
                u32 bh0[2], bh1[2];
                int w0 = ks * 8 + tid;
                bh0[0] = smu[O_W2 + f0 * 68 + w0]; bh0[1] = smu[O_W2 + f0 * 68 + w0 + 4];
                bh1[0] = smu[O_W2 + f1 * 68 + w0]; bh1[1] = smu[O_W2 + f1 * 68 + w0 + 4];
                MMA16816(da0, AH2[ks], bh0);
                MMA16816(da1, AH2[ks], bh1);
                MMA16816(db0, AL2[ks], bh0);
                MMA16816(db1, AL2[ks], bh1);
            }
            float2 ba = *(const float2*)(b2s + np * 16 + tid * 2);
            float2 bb = *(const float2*)(b2s + np * 16 + 8 + tid * 2);
            if (dst0 >= 0) {
                float* base = g_agg + (size_t)dst0 * 128 + np * 16 + tid * 2;
                float m0 = (da0[0] + db0[0] + ba.x) * C0 * h00.x;
                float m1 = (da0[1] + db0[1] + ba.y) * C0 * h00.y;
                asm volatile("red.global.add.v2.f32 [%0], {%1, %2};"
                             :: "l"(base), "f"(m0), "f"(m1) : "memory");
                float m2 = (da1[0] + db1[0] + bb.x) * C0 * h01.x;
                float m3 = (da1[1] + db1[1] + bb.y) * C0 * h01.y;
                asm volatile("red.global.add.v2.f32 [%0], {%1, %2};"
                             :: "l"(base + 8), "f"(m2), "f"(m3) : "memory");
            }
            if (dst8 >= 0) {
                float* base = g_agg + (size_t)dst8 * 128 + np * 16 + tid * 2;
                float m0 = (da0[2] + db0[2] + ba.x) * C8 * h80.x;
                float m1 = (da0[3] + db0[3] + ba.y) * C8 * h80.y;
                asm volatile("red.global.add.v2.f32 [%0], {%1, %2};"
                             :: "l"(base), "f"(m0), "f"(m1) : "memory");
                float m2 = (da1[2] + db1[2] + bb.x) * C8 * h81.x;
                float m3 = (da1[3] + db1[3] + bb.y) * C8 * h81.y;
                asm volatile("red.global.add.v2.f32 [%0], {%1, %2};"
                             :: "l"(base + 8), "f"(m2), "f"(m3) : "memory");
            }
            h00 = nh00; h01 = nh01; h80 = nh80; h81 = nh81;
        }
        __syncwarp();
    }
}

// ---------------------------------------------------------------- cleanup
__global__ void cleanup_kernel() {
    int idx = blockIdx.x * blockDim.x + threadIdx.x;
    int stride = gridDim.x * blockDim.x;
    for (int i = idx; i < N_NODES * N_FILT; i += stride) g_agg[i] = 0.0f;
    if (idx < N_COLORS) g_cnt[idx] = 0;
}

// ---------------------------------------------------------------- launch
extern "C" void kernel_launch(void* const* d_in, const int* in_sizes, int n_in,
                              void* d_out, int out_size) {
    const float* x    = (const float*)d_in[0];
    const int*   ei   = (const int*)d_in[1];
    const float* ew   = (const float*)d_in[2];
    const float* attr = (const float*)d_in[3];
    const int*   col  = (const int*)d_in[4];
    const float* m1w  = (const float*)d_in[5];
    const float* m1b  = (const float*)d_in[6];
    const float* m2w  = (const float*)d_in[7];
    const float* m2b  = (const float*)d_in[8];
    const float* l1w  = (const float*)d_in[9];
    const float* l2w  = (const float*)d_in[10];
    const float* l2b  = (const float*)d_in[11];
    const float* lw   = (const float*)d_in[12];
    const float* lb   = (const float*)d_in[13];
    float* out = (float*)d_out;

    float* gh_ptr;
    float* gagg_ptr;
    cudaGetSymbolAddress((void**)&gh_ptr, g_h);
    cudaGetSymbolAddress((void**)&gagg_ptr, g_agg);

    cudaFuncSetAttribute(edge_kernel, cudaFuncAttributeMaxDynamicSharedMemorySize, EDGE_SMEM);
    cudaFuncSetAttribute(mm_kernel<0>, cudaFuncAttributeMaxDynamicSharedMemorySize, MM_SMEM);
    cudaFuncSetAttribute(mm_kernel<1>, cudaFuncAttributeMaxDynamicSharedMemorySize, MM_SMEM);
    cudaFuncSetAttribute(mm_kernel<2>, cudaFuncAttributeMaxDynamicSharedMemorySize, MM_SMEM);

    hist_kernel<<<512, 256>>>(col);
    offset_kernel<<<1, 1>>>();
    scatter_kernel<<<SC_NB, 256>>>(col);
    mm_kernel<0><<<MM_NB, 256, MM_SMEM>>>(x, l1w, nullptr, gh_ptr);              // lin1
    edge_kernel<<<NCHUNK, 256, EDGE_SMEM>>>(ei, ew, attr, col, m1w, m1b, m2w, m2b);
    mm_kernel<1><<<MM_NB, 256, MM_SMEM>>>(gagg_ptr, l2w, l2b, gh_ptr);           // mid = ssp(agg@W2+b2)
    mm_kernel<2><<<MM_NB, 256, MM_SMEM>>>(gh_ptr, lw, lb, out);                  // out = mid@W3+b3
    cleanup_kernel<<<2048, 256>>>();
}

// round 17
// speedup vs baseline: 4.2051x; 1.0402x over previous
#include <cuda_runtime.h>
#include <cuda_fp16.h>
#include <cstdint>

#define N_NODES 50000
#define N_EDGES 1000000
#define HIDDEN  128
#define N_GAUSS 50
#define N_FILT  128
#define N_COLORS 4
#define CUTOFF_R 10.0f
#define LOG2F_  0.6931471805599453f
#define PI_F    3.14159265358979323846f

#define CH 1024              // edges per block-chunk (color-aligned)
#define NCHUNK 981
#define PERM_SZ (NCHUNK*CH)
#define SC_BS 4096
#define SC_NB 245
#define MM_NB 391            // ceil(N_NODES / 128)
#define FULLM 0xffffffffu

// ---- scratch (static device globals; zero-initialized at module load) ----
__device__ float g_h[N_NODES * HIDDEN];     // lin1 out; later reused for mid
__device__ float g_agg[N_NODES * N_FILT];
__device__ int   g_perm[PERM_SZ];           // color-sorted (edge id + 1), 0 = pad
__device__ int   g_cnt[N_COLORS];
__device__ int   g_cur[N_COLORS];

__device__ __forceinline__ float ssp(float v) {
    return fmaxf(v, 0.0f) + __logf(1.0f + __expf(-fabsf(v))) - LOG2F_;
}

typedef uint32_t u32;

// pack two f32 -> f16x2 {lo, hi}
__device__ __forceinline__ u32 pk_h(float lo, float hi) {
    u32 r;
    asm("cvt.rn.f16x2.f32 %0, %1, %2;" : "=r"(r) : "f"(hi), "f"(lo));
    return r;
}
__device__ __forceinline__ float hr(float v) {   // residual after fp16 truncation
    return v - __half2float(__float2half_rn(v));
}

// m16n8k16 row.col f32.f16.f16.f32
#define MMA16816(d, a, b) \
    asm volatile("mma.sync.aligned.m16n8k16.row.col.f32.f16.f16.f32 " \
        "{%0,%1,%2,%3}, {%4,%5,%6,%7}, {%8,%9}, {%0,%1,%2,%3};" \
        : "+f"((d)[0]), "+f"((d)[1]), "+f"((d)[2]), "+f"((d)[3]) \
        : "r"((a)[0]), "r"((a)[1]), "r"((a)[2]), "r"((a)[3]), \
          "r"((b)[0]), "r"((b)[1]))

// ---------------------------------------------------------------- histogram (ballot)
__global__ void hist_kernel(const int* __restrict__ colors) {
    __shared__ int sh[N_COLORS];
    if (threadIdx.x < N_COLORS) sh[threadIdx.x] = 0;
    __syncthreads();
    int idx = blockIdx.x * blockDim.x + threadIdx.x;
    int stride = gridDim.x * blockDim.x;
    int iters = (N_EDGES + stride - 1) / stride;
    for (int k = 0; k < iters; k++) {
        int i = idx + k * stride;
        int ci = (i < N_EDGES) ? colors[i] : -1;
#pragma unroll
        for (int c = 0; c < N_COLORS; c++) {
            u32 m = __ballot_sync(FULLM, ci == c);
            if ((threadIdx.x & 31) == 0 && m) atomicAdd(&sh[c], __popc(m));
        }
    }
    __syncthreads();
    if (threadIdx.x < N_COLORS) atomicAdd(&g_cnt[threadIdx.x], sh[threadIdx.x]);
}

// ---------------------------------------------------------------- offsets (+ g_cnt reset)
__global__ void offset_kernel() {
    if (blockIdx.x == 0 && threadIdx.x == 0) {
        int b = 0;
        for (int c = 0; c < N_COLORS; c++) {
            g_cur[c] = b;
            b += (g_cnt[c] + CH - 1) / CH * CH;
            g_cnt[c] = 0;                       // restore invariant for next call
        }
    }
}

// ---------------------------------------------------------------- generic HMMA node GEMM body
// out[r,:] = act(A[r,:] @ W^T + bias); W single fp16 (paired-word layout, stride 72),
// A fp16 hi/lo 2-term. MODE: 0 = plain, 1 = bias + ssp, 2 = bias only.
// If Az != nullptr, the rows of Az this block consumed are zeroed (fused cleanup).
#define MM_SMEM ((9216 + 128) * 4)

template<int MODE>
__device__ __forceinline__ void mm_body(
    const float* __restrict__ A, float* Az,
    const float* __restrict__ W, const float* __restrict__ bias,
    float* __restrict__ out, int bid, u32* smu)
{
    int t = threadIdx.x;
    for (int i = t; i < 128 * 64; i += 256) {
        int f = i >> 6, w = i & 63;
        int ks = w >> 3, r = w & 7;
        int pos = f * 72 + ks * 8 + ((r < 4) ? 2 * r : 2 * (r - 4) + 1);
        float2 v = *(const float2*)(W + f * 128 + w * 2);
        smu[pos] = pk_h(v.x, v.y);
    }
    float* bs = (float*)(smu + 9216);
    if (MODE != 0 && t < 128) bs[t] = bias[t];
    __syncthreads();

    int wid = t >> 5, lane = t & 31;
    int gr = lane >> 2, tid = lane & 3;
    int r0 = bid * 128 + wid * 16 + gr;
    int r1 = r0 + 8;
    bool v0r = r0 < N_NODES, v1r = r1 < N_NODES;
    const float* a0 = A + (size_t)(v0r ? r0 : 0) * 128;
    const float* a1 = A + (size_t)(v1r ? r1 : 0) * 128;

    u32 AH[8][4], AL[8][4];
#pragma unroll
    for (int ks = 0; ks < 8; ks++) {
        int c0 = ks * 16 + tid * 2, c1 = c0 + 8;
        float2 z = make_float2(0.0f, 0.0f);
        float2 x0 = v0r ? *(const float2*)(a0 + c0) : z;
        float2 x1 = v1r ? *(const float2*)(a1 + c0) : z;
        float2 x2 = v0r ? *(const float2*)(a0 + c1) : z;
        float2 x3 = v1r ? *(const float2*)(a1 + c1) : z;
        AH[ks][0] = pk_h(x0.x, x0.y); AL[ks][0] = pk_h(hr(x0.x), hr(x0.y));
        AH[ks][1] = pk_h(x1.x, x1.y); AL[ks][1] = pk_h(hr(x1.x), hr(x1.y));
        AH[ks][2] = pk_h(x2.x, x2.y); AL[ks][2] = pk_h(hr(x2.x), hr(x2.y));
        AH[ks][3] = pk_h(x3.x, x3.y); AL[ks][3] = pk_h(hr(x3.x), hr(x3.y));
    }
    if (Az) {
        float2 z = make_float2(0.0f, 0.0f);
#pragma unroll
        for (int ks = 0; ks < 8; ks++) {
            int c0 = ks * 16 + tid * 2, c1 = c0 + 8;
            if (v0r) {
                *(float2*)(Az + (size_t)r0 * 128 + c0) = z;
                *(float2*)(Az + (size_t)r0 * 128 + c1) = z;
            }
            if (v1r) {
                *(float2*)(Az + (size_t)r1 * 128 + c0) = z;
                *(float2*)(Az + (size_t)r1 * 128 + c1) = z;
            }
        }
    }

#pragma unroll
    for (int np = 0; np < 8; np++) {
        float da0[4] = {0, 0, 0, 0}, db0[4] = {0, 0, 0, 0};
        float da1[4] = {0, 0, 0, 0}, db1[4] = {0, 0, 0, 0};
        int f0 = np * 16 + gr, f1 = f0 + 8;
#pragma unroll
        for (int ks = 0; ks < 8; ks++) {
            uint2 bb0 = *(const uint2*)(smu + f0 * 72 + ks * 8 + 2 * tid);
            uint2 bb1 = *(const uint2*)(smu + f1 * 72 + ks * 8 + 2 * tid);
            u32 bh0[2] = {bb0.x, bb0.y};
            u32 bh1[2] = {bb1.x, bb1.y};
            MMA16816(da0, AH[ks], bh0);
            MMA16816(da1, AH[ks], bh1);
            MMA16816(db0, AL[ks], bh0);
            MMA16816(db1, AL[ks], bh1);
        }
        float s00 = da0[0] + db0[0], s01 = da0[1] + db0[1];
        float s02 = da0[2] + db0[2], s03 = da0[3] + db0[3];
        float s10 = da1[0] + db1[0], s11 = da1[1] + db1[1];
        float s12 = da1[2] + db1[2], s13 = da1[3] + db1[3];
        if (MODE != 0) {
            float2 ba = *(const float2*)(bs + np * 16 + tid * 2);
            float2 bb = *(const float2*)(bs + np * 16 + 8 + tid * 2);
            s00 += ba.x; s01 += ba.y; s02 += ba.x; s03 += ba.y;
            s10 += bb.x; s11 += bb.y; s12 += bb.x; s13 += bb.y;
        }
        if (MODE == 1) {
            s00 = ssp(s00); s01 = ssp(s01); s02 = ssp(s02); s03 = ssp(s03);
            s10 = ssp(s10); s11 = ssp(s11); s12 = ssp(s12); s13 = ssp(s13);
        }
        int col = np * 16 + tid * 2;
        if (v0r) {
            *(float2*)(out + (size_t)r0 * 128 + col) = make_float2(s00, s01);
            *(float2*)(out + (size_t)r0 * 128 + col + 8) = make_float2(s10, s11);
        }
        if (v1r) {
            *(float2*)(out + (size_t)r1 * 128 + col) = make_float2(s02, s03);
            *(float2*)(out + (size_t)r1 * 128 + col + 8) = make_float2(s12, s13);
        }
    }
}

template<int MODE>
__global__ void __launch_bounds__(256, 2) mm_kernel(
    const float* __restrict__ A, float* Az,
    const float* __restrict__ W, const float* __restrict__ bias,
    float* __restrict__ out)
{
    extern __shared__ u32 smu[];
    mm_body<MODE>(A, Az, W, bias, out, blockIdx.x, smu);
}

// ---------------------------------------------------------------- fused scatter + lin1
__global__ void __launch_bounds__(256, 2) scatter_mm0_kernel(
    const int* __restrict__ colors,
    const float* __restrict__ x,
    const float* __restrict__ w)
{
    extern __shared__ u32 smu[];
    if (blockIdx.x < SC_NB) {
        int* s_cnt = (int*)smu;
        int* s_base = s_cnt + N_COLORS;
        int t = threadIdx.x;
        if (t < N_COLORS) s_cnt[t] = 0;
        __syncthreads();
        int start = blockIdx.x * SC_BS;
        int end = min(start + SC_BS, N_EDGES);
        for (int i = start + t; i < end; i += blockDim.x) atomicAdd(&s_cnt[colors[i]], 1);
        __syncthreads();
        if (t < N_COLORS) { s_base[t] = atomicAdd(&g_cur[t], s_cnt[t]); s_cnt[t] = 0; }
        __syncthreads();
        for (int i = start + t; i < end; i += blockDim.x) {
            int c = colors[i];
            int pos = s_base[c] + atomicAdd(&s_cnt[c], 1);
            g_perm[pos] = i + 1;
        }
    } else {
        mm_body<0>(x, nullptr, w, nullptr, g_h, blockIdx.x - SC_NB, smu);
    }
}

// ---------------------------------------------------------------- HMMA fused edge kernel
// fp16 2-term; paired-word W layout: W1 stride 40, W2 stride 72 (both ≡8 mod 32).
#define O_W1   0                    // 128*40 = 5120
#define O_W2   5120                 // 128*72 = 9216
#define O_B1   14336
#define O_B2   14464
#define O_META 14592
#define EDGE_SMEM ((14592 + 512) * 4)

__global__ void __launch_bounds__(256, 2) edge_kernel(
    const int* __restrict__ edge_index,
    const float* __restrict__ ew,
    const float* __restrict__ attr,
    const int* __restrict__ colors,
    const float* __restrict__ m1w, const float* __restrict__ m1b,
    const float* __restrict__ m2w, const float* __restrict__ m2b)
{
    extern __shared__ u32 smu[];
    int t = threadIdx.x;
    int chunk0 = blockIdx.x * CH;
    int p0c = g_perm[chunk0] - 1;
    if (p0c < 0) return;
    int c = colors[p0c];

    {
        const float* w1 = m1w + (size_t)c * 128 * N_GAUSS;
        for (int i = t; i < 128 * 32; i += 256) {
            int f = i >> 5, w = i & 31;
            int ks = w >> 3, r = w & 7;
            int pos = O_W1 + f * 40 + ks * 8 + ((r < 4) ? 2 * r : 2 * (r - 4) + 1);
            int k0 = w * 2, k1 = w * 2 + 1;
            float v0 = (k0 < N_GAUSS) ? w1[f * N_GAUSS + k0] : 0.0f;
            float v1 = (k1 < N_GAUSS) ? w1[f * N_GAUSS + k1] : 0.0f;
            smu[pos] = pk_h(v0, v1);
        }
        const float* w2 = m2w + (size_t)c * 128 * 128;
        for (int i = t; i < 128 * 64; i += 256) {
            int f = i >> 6, w = i & 63;
            int ks = w >> 3, r = w & 7;
            int pos = O_W2 + f * 72 + ks * 8 + ((r < 4) ? 2 * r : 2 * (r - 4) + 1);
            float2 v = *(const float2*)(w2 + f * 128 + w * 2);
            smu[pos] = pk_h(v.x, v.y);
        }
        if (t < 128) {
            ((float*)smu)[O_B1 + t] = m1b[c * 128 + t];
            ((float*)smu)[O_B2 + t] = m2b[c * 128 + t];
        }
    }
    __syncthreads();

    int wid = t >> 5, lane = t & 31;
    int gr = lane >> 2, tid = lane & 3;
    int*   s_p    = (int*)(smu + O_META + wid * 64);
    int*   s_src  = s_p + 16;
    int*   s_dst  = s_p + 32;
    float* s_C    = (float*)(s_p + 48);
    const float* b1s = (const float*)(smu + O_B1);
    const float* b2s = (const float*)(smu + O_B2);

    for (int it = 0; it < 8; it++) {
        int ebase = chunk0 + wid * 128 + it * 16;

        if (lane < 16) {
            int p = g_perm[ebase + lane] - 1;
            int sr = 0, ds = -1;
            float C = 0.0f;
            if (p >= 0) {
                sr = edge_index[p];
                ds = edge_index[N_EDGES + p];
                C = 0.5f * (__cosf(ew[p] * (PI_F / CUTOFF_R)) + 1.0f);
            }
            s_p[lane] = p; s_src[lane] = sr; s_dst[lane] = ds; s_C[lane] = C;
        }
        __syncwarp();

        // ---- attr A-fragments from gmem (fp16 hi/lo), K=64 -> 4 k-steps ----
        int pg = s_p[gr], p8 = s_p[gr + 8];
        const float* ar0 = attr + (size_t)(pg < 0 ? 0 : pg) * N_GAUSS;
        const float* ar8 = attr + (size_t)(p8 < 0 ? 0 : p8) * N_GAUSS;
        u32 AH1[4][4], AL1[4][4];
#pragma unroll
        for (int ks = 0; ks < 4; ks++) {
            int c0 = ks * 16 + tid * 2;
            int c1 = c0 + 8;
            float2 z = make_float2(0.0f, 0.0f);
            float2 v0 = (pg >= 0 && c0 < N_GAUSS) ? *(const float2*)(ar0 + c0) : z;
            float2 v1 = (p8 >= 0 && c0 < N_GAUSS) ? *(const float2*)(ar8 + c0) : z;
            float2 v2 = (pg >= 0 && c1 < N_GAUSS) ? *(const float2*)(ar0 + c1) : z;
            float2 v3 = (p8 >= 0 && c1 < N_GAUSS) ? *(const float2*)(ar8 + c1) : z;
            AH1[ks][0] = pk_h(v0.x, v0.y); AL1[ks][0] = pk_h(hr(v0.x), hr(v0.y));
            AH1[ks][1] = pk_h(v1.x, v1.y); AL1[ks][1] = pk_h(hr(v1.x), hr(v1.y));
            AH1[ks][2] = pk_h(v2.x, v2.y); AL1[ks][2] = pk_h(hr(v2.x), hr(v2.y));
            AH1[ks][3] = pk_h(v3.x, v3.y); AL1[ks][3] = pk_h(hr(v3.x), hr(v3.y));
        }

        // ---- MLP1: 2 chains per n-tile; convert directly into MLP2 A-frags ----
        u32 AH2[8][4], AL2[8][4];
#pragma unroll
        for (int np = 0; np < 8; np++) {
            float da0[4] = {0, 0, 0, 0}, db0[4] = {0, 0, 0, 0};
            float da1[4] = {0, 0, 0, 0}, db1[4] = {0, 0, 0, 0};
            int f0 = np * 16 + gr;
            int f1 = f0 + 8;
#pragma unroll
            for (int ks = 0; ks < 4; ks++) {
                uint2 bb0 = *(const uint2*)(smu + O_W1 + f0 * 40 + ks * 8 + 2 * tid);
                uint2 bb1 = *(const uint2*)(smu + O_W1 + f1 * 40 + ks * 8 + 2 * tid);
                u32 bh0[2] = {bb0.x, bb0.y};
                u32 bh1[2] = {bb1.x, bb1.y};
                MMA16816(da0, AH1[ks], bh0);
                MMA16816(da1, AH1[ks], bh1);
                MMA16816(db0, AL1[ks], bh0);
                MMA16816(db1, AL1[ks], bh1);
            }
            float2 ba = *(const float2*)(b1s + np * 16 + tid * 2);
            float2 bb = *(const float2*)(b1s + np * 16 + 8 + tid * 2);
            float h00 = ssp(da0[0] + db0[0] + ba.x), h01 = ssp(da0[1] + db0[1] + ba.y);
            float h02 = ssp(da0[2] + db0[2] + ba.x), h03 = ssp(da0[3] + db0[3] + ba.y);
            float h10 = ssp(da1[0] + db1[0] + bb.x), h11 = ssp(da1[1] + db1[1] + bb.y);
            float h12 = ssp(da1[2] + db1[2] + bb.x), h13 = ssp(da1[3] + db1[3] + bb.y);
            AH2[np][0] = pk_h(h00, h01); AL2[np][0] = pk_h(hr(h00), hr(h01));
            AH2[np][1] = pk_h(h02, h03); AL2[np][1] = pk_h(hr(h02), hr(h03));
            AH2[np][2] = pk_h(h10, h11); AL2[np][2] = pk_h(hr(h10), hr(h11));
            AH2[np][3] = pk_h(h12, h13); AL2[np][3] = pk_h(hr(h12), hr(h13));
        }

        // ---- MLP2 + epilogue, h[src] gather pipelined one n-pair ahead ----
        int   dst0 = s_dst[gr],     dst8 = s_dst[gr + 8];
        float C0   = s_C[gr],       C8   = s_C[gr + 8];
        const float* hb0 = g_h + (size_t)s_src[gr] * 128;
        const float* hb8 = g_h + (size_t)s_src[gr + 8] * 128;

        float2 h00 = *(const float2*)(hb0 + tid * 2);
        float2 h01 = *(const float2*)(hb0 + 8 + tid * 2);
        float2 h80 = *(const float2*)(hb8 + tid * 2);
        float2 h81 = *(const float2*)(hb8 + 8 + tid * 2);

#pragma unroll
        for (int np = 0; np < 8; np++) {
            float da0[4] = {0, 0, 0, 0}, db0[4] = {0, 0, 0, 0};
            float da1[4] = {0, 0, 0, 0}, db1[4] = {0, 0, 0, 0};
            float2 nh00, nh01, nh80, nh81;
            if (np < 7) {
                int fo = (np + 1) * 16 + tid * 2;
                nh00 = *(const float2*)(hb0 + fo);
                nh01 = *(const float2*)(hb0 + fo + 8);
                nh80 = *(const float2*)(hb8 + fo);
                nh81 = *(const float2*)(hb8 + fo + 8);
            }
            int f0 = np * 16 + gr;
            int f1 = f0 + 8;
#pragma unroll
            for (int ks = 0; ks < 8; ks++) {
                uint2 bb0 = *(const uint2*)(smu + O_W2 + f0 * 72 + ks * 8 + 2 * tid);
                uint2 bb1 = *(const uint2*)(smu + O_W2 + f1 * 72 + ks * 8 + 2 * tid);
                u32 bh0[2] = {bb0.x, bb0.y};
                u32 bh1[2] = {bb1.x, bb1.y};
                MMA16816(da0, AH2[ks], bh0);
                MMA16816(da1, AH2[ks], bh1);
                MMA16816(db0, AL2[ks], bh0);
                MMA16816(db1, AL2[ks], bh1);
            }
            float2 ba = *(const float2*)(b2s + np * 16 + tid * 2);
            float2 bb = *(const float2*)(b2s + np * 16 + 8 + tid * 2);
            if (dst0 >= 0) {
                float* base = g_agg + (size_t)dst0 * 128 + np * 16 + tid * 2;
                float m0 = (da0[0] + db0[0] + ba.x) * C0 * h00.x;
                float m1 = (da0[1] + db0[1] + ba.y) * C0 * h00.y;
                asm volatile("red.global.add.v2.f32 [%0], {%1, %2};"
                             :: "l"(base), "f"(m0), "f"(m1) : "memory");
                float m2 = (da1[0] + db1[0] + bb.x) * C0 * h01.x;
                float m3 = (da1[1] + db1[1] + bb.y) * C0 * h01.y;
                asm volatile("red.global.add.v2.f32 [%0], {%1, %2};"
                             :: "l"(base + 8), "f"(m2), "f"(m3) : "memory");
            }
            if (dst8 >= 0) {
                float* base = g_agg + (size_t)dst8 * 128 + np * 16 + tid * 2;
                float m0 = (da0[2] + db0[2] + ba.x) * C8 * h80.x;
                float m1 = (da0[3] + db0[3] + ba.y) * C8 * h80.y;
                asm volatile("red.global.add.v2.f32 [%0], {%1, %2};"
                             :: "l"(base), "f"(m0), "f"(m1) : "memory");
                float m2 = (da1[2] + db1[2] + bb.x) * C8 * h81.x;
                float m3 = (da1[3] + db1[3] + bb.y) * C8 * h81.y;
                asm volatile("red.global.add.v2.f32 [%0], {%1, %2};"
                             :: "l"(base + 8), "f"(m2), "f"(m3) : "memory");
            }
            h00 = nh00; h01 = nh01; h80 = nh80; h81 = nh81;
        }
        __syncwarp();
    }
}

// ---------------------------------------------------------------- launch
extern "C" void kernel_launch(void* const* d_in, const int* in_sizes, int n_in,
                              void* d_out, int out_size) {
    const float* x    = (const float*)d_in[0];
    const int*   ei   = (const int*)d_in[1];
    const float* ew   = (const float*)d_in[2];
    const float* attr = (const float*)d_in[3];
    const int*   col  = (const int*)d_in[4];
    const float* m1w  = (const float*)d_in[5];
    const float* m1b  = (const float*)d_in[6];
    const float* m2w  = (const float*)d_in[7];
    const float* m2b  = (const float*)d_in[8];
    const float* l1w  = (const float*)d_in[9];
    const float* l2w  = (const float*)d_in[10];
    const float* l2b  = (const float*)d_in[11];
    const float* lw   = (const float*)d_in[12];
    const float* lb   = (const float*)d_in[13];
    float* out = (float*)d_out;

    float* gh_ptr;
    float* gagg_ptr;
    cudaGetSymbolAddress((void**)&gh_ptr, g_h);
    cudaGetSymbolAddress((void**)&gagg_ptr, g_agg);

    cudaFuncSetAttribute(edge_kernel, cudaFuncAttributeMaxDynamicSharedMemorySize, EDGE_SMEM);
    cudaFuncSetAttribute(scatter_mm0_kernel, cudaFuncAttributeMaxDynamicSharedMemorySize, MM_SMEM);
    cudaFuncSetAttribute(mm_kernel<1>, cudaFuncAttributeMaxDynamicSharedMemorySize, MM_SMEM);
    cudaFuncSetAttribute(mm_kernel<2>, cudaFuncAttributeMaxDynamicSharedMemorySize, MM_SMEM);

    hist_kernel<<<512, 256>>>(col);
    offset_kernel<<<1, 1>>>();
    scatter_mm0_kernel<<<SC_NB + MM_NB, 256, MM_SMEM>>>(col, x, l1w);            // scatter + lin1
    edge_kernel<<<NCHUNK, 256, EDGE_SMEM>>>(ei, ew, attr, col, m1w, m1b, m2w, m2b);
    mm_kernel<1><<<MM_NB, 256, MM_SMEM>>>(gagg_ptr, gagg_ptr, l2w, l2b, gh_ptr); // mid + zero g_agg
    mm_kernel<2><<<MM_NB, 256, MM_SMEM>>>(gh_ptr, nullptr, lw, lb, out);         // out = mid@W3+b3
}